// round 1
// baseline (speedup 1.0000x reference)
#include <cuda_runtime.h>

#define Bv 8
#define Nv 256
#define Hv 128
#define EPSv 1e-5f
#define X_ELEMS (Bv*Nv*Hv)          /* 262144  */
#define E_ELEMS (Bv*Nv*Nv*Hv)       /* 67108864 */

#define SW_PITCH 132
#define SE_PITCH 132
#define SMEM_FLOATS (128*SW_PITCH + 64*SE_PITCH)
#define SMEM_BYTES  (SMEM_FLOATS*4)

// ---- scratch (static device globals; no runtime allocation) ----
__device__ float g_e_tmp[E_ELEMS];      // e_new (pre-BN), 256 MB
__device__ float g_vx[X_ELEMS];
__device__ float g_vnx[X_ELEMS];
__device__ float g_unx[X_ELEMS];
__device__ float g_xnew[X_ELEMS];
__device__ float g_esum[Hv];
__device__ float g_esumsq[Hv];
__device__ float g_xsum[Hv];
__device__ float g_xsumsq[Hv];
__device__ float g_escale[Hv];
__device__ float g_eshift[Hv];
__device__ float g_xscale[Hv];
__device__ float g_xshift[Hv];

// 64(j) x 128(h) output tile GEMM over K=128.
// sW[k*SW_PITCH + h] = W[h][k]; sE[j*SE_PITCH + k] = in[j][k].
// Thread (r = tid>>4, c = tid&15) computes j in [r*4, r*4+4), h in {c*4..c*4+3, 64+c*4..64+c*4+3}.
#define GEMM_TILE(acc, sW, sE, r, hA, hB)                                   \
  {                                                                          \
    _Pragma("unroll")                                                        \
    for (int kk = 0; kk < 128; kk += 4) {                                    \
      float4 ev[4];                                                          \
      _Pragma("unroll")                                                      \
      for (int jj = 0; jj < 4; jj++)                                         \
        ev[jj] = *(const float4*)(sE + ((r)*4+jj)*SE_PITCH + kk);            \
      _Pragma("unroll")                                                      \
      for (int kq = 0; kq < 4; kq++) {                                       \
        float4 wa = *(const float4*)(sW + (kk+kq)*SW_PITCH + (hA));          \
        float4 wb = *(const float4*)(sW + (kk+kq)*SW_PITCH + (hB));          \
        _Pragma("unroll")                                                    \
        for (int jj = 0; jj < 4; jj++) {                                     \
          float ee = (kq==0)?ev[jj].x:(kq==1)?ev[jj].y:(kq==2)?ev[jj].z:ev[jj].w; \
          acc[jj][0] += ee*wa.x; acc[jj][1] += ee*wa.y;                      \
          acc[jj][2] += ee*wa.z; acc[jj][3] += ee*wa.w;                      \
          acc[jj][4] += ee*wb.x; acc[jj][5] += ee*wb.y;                      \
          acc[jj][6] += ee*wb.z; acc[jj][7] += ee*wb.w;                      \
        }                                                                    \
      }                                                                      \
    }                                                                        \
  }

__global__ void zero_stats_kernel() {
    int t = threadIdx.x;
    if (t < Hv) { g_esum[t]=0.f; g_esumsq[t]=0.f; g_xsum[t]=0.f; g_xsumsq[t]=0.f; }
}

// K1: Vx = x@Ve_w.T+Ve_b ; Vnx = x@Vn_w.T+Vn_b ; Unx = x@Un_w.T+Un_b
// grid (32 row-tiles, 3 matrices), block 256
__global__ __launch_bounds__(256, 2) void node_linear_kernel(
    const float* __restrict__ x,
    const float* __restrict__ Ve_w, const float* __restrict__ Ve_b,
    const float* __restrict__ Vn_w, const float* __restrict__ Vn_b,
    const float* __restrict__ Un_w, const float* __restrict__ Un_b)
{
    extern __shared__ float sm[];
    float* sW = sm;
    float* sE = sm + 128*SW_PITCH;
    int tid = threadIdx.x;
    int mat = blockIdx.y;
    const float* W    = (mat==0) ? Ve_w : (mat==1) ? Vn_w : Un_w;
    const float* bias = (mat==0) ? Ve_b : (mat==1) ? Vn_b : Un_b;
    float* out        = (mat==0) ? g_vx : (mat==1) ? g_vnx : g_unx;
    int row0 = blockIdx.x * 64;

    #pragma unroll 8
    for (int it = 0; it < 64; ++it) {
        int g = it*256 + tid;
        sW[(g & 127)*SW_PITCH + (g >> 7)] = W[g];   // sW[k][h] = W[h][k]
    }
    #pragma unroll
    for (int it = 0; it < 8; ++it) {
        int idx = it*256 + tid;
        int rr = idx >> 5, kk = (idx & 31)*4;
        *(float4*)(sE + rr*SE_PITCH + kk) = *(const float4*)(x + (row0+rr)*Hv + kk);
    }
    __syncthreads();

    int c = tid & 15, r = tid >> 4;
    int hA = c*4, hB = 64 + c*4;
    float acc[4][8];
    #pragma unroll
    for (int jj=0;jj<4;jj++)
        #pragma unroll
        for (int q=0;q<8;q++) acc[jj][q]=0.f;

    GEMM_TILE(acc, sW, sE, r, hA, hB);

    float bA[4], bB[4];
    #pragma unroll
    for (int q=0;q<4;q++){ bA[q]=bias[hA+q]; bB[q]=bias[hB+q]; }
    #pragma unroll
    for (int jj=0;jj<4;jj++){
        int row = row0 + r*4 + jj;
        float oA[4], oB[4];
        #pragma unroll
        for (int q=0;q<4;q++){ oA[q]=acc[jj][q]+bA[q]; oB[q]=acc[jj][4+q]+bB[q]; }
        *(float4*)(out + row*Hv + hA) = *(float4*)oA;
        *(float4*)(out + row*Hv + hB) = *(float4*)oB;
    }
}

// K2: per-(b,i): e_new = e@Ue_w.T + Ue_b + Vx_i + Vx_j ; gate=sigmoid(e_new);
//     agg = sum_j gate*Vnx_j ; x_new = Unx + agg ; BN sums via atomics.
// grid 2048, block 256
__global__ __launch_bounds__(256, 2) void edge_fused_kernel(
    const float* __restrict__ e,
    const float* __restrict__ Ue_w, const float* __restrict__ Ue_b)
{
    extern __shared__ float sm[];
    float* sW = sm;
    float* sE = sm + 128*SW_PITCH;
    float* sRed = sE;                    // alias: used after GEMM tiles done
    int tid = threadIdx.x;
    int bi = blockIdx.x;                 // b*256 + i
    int b = bi >> 8;
    const float* erow = e + (size_t)bi * Nv * Hv;     // e[b,i,:,:]
    float* etmp = g_e_tmp + (size_t)bi * Nv * Hv;

    #pragma unroll 8
    for (int it = 0; it < 64; ++it) {
        int g = it*256 + tid;
        sW[(g & 127)*SW_PITCH + (g >> 7)] = Ue_w[g];
    }

    int c = tid & 15, r = tid >> 4;
    int hA = c*4, hB = 64 + c*4;

    float biasA[4], biasB[4];
    #pragma unroll
    for (int q=0;q<4;q++){
        biasA[q] = Ue_b[hA+q] + g_vx[bi*Hv + hA + q];
        biasB[q] = Ue_b[hB+q] + g_vx[bi*Hv + hB + q];
    }
    float aggl[8], suml[8], sql[8];
    #pragma unroll
    for (int q=0;q<8;q++){ aggl[q]=0.f; suml[q]=0.f; sql[q]=0.f; }

    __syncthreads();   // sW visible

    #pragma unroll 1
    for (int jt = 0; jt < 4; ++jt) {
        if (jt) __syncthreads();         // protect previous tile reads
        #pragma unroll
        for (int it = 0; it < 8; ++it) {
            int idx = it*256 + tid;
            int rr = idx >> 5, kk = (idx & 31)*4;
            *(float4*)(sE + rr*SE_PITCH + kk) =
                *(const float4*)(erow + (jt*64 + rr)*Hv + kk);
        }
        __syncthreads();

        float acc[4][8];
        #pragma unroll
        for (int jj=0;jj<4;jj++)
            #pragma unroll
            for (int q=0;q<8;q++) acc[jj][q]=0.f;

        GEMM_TILE(acc, sW, sE, r, hA, hB);

        #pragma unroll
        for (int jj=0;jj<4;jj++){
            int j = jt*64 + r*4 + jj;
            const float* vxj = g_vx  + (b*Nv + j)*Hv;
            const float* vnj = g_vnx + (b*Nv + j)*Hv;
            float vxA[4], vxB[4], vnA[4], vnB[4];
            *(float4*)vxA = *(const float4*)(vxj + hA);
            *(float4*)vxB = *(const float4*)(vxj + hB);
            *(float4*)vnA = *(const float4*)(vnj + hA);
            *(float4*)vnB = *(const float4*)(vnj + hB);
            float oA[4], oB[4];
            #pragma unroll
            for (int q=0;q<4;q++){
                float v = acc[jj][q] + biasA[q] + vxA[q];
                float gte = 1.f / (1.f + __expf(-v));
                aggl[q] += gte * vnA[q];
                suml[q] += v; sql[q] += v*v;
                oA[q] = v;
                float v2 = acc[jj][4+q] + biasB[q] + vxB[q];
                float gte2 = 1.f / (1.f + __expf(-v2));
                aggl[4+q] += gte2 * vnB[q];
                suml[4+q] += v2; sql[4+q] += v2*v2;
                oB[q] = v2;
            }
            *(float4*)(etmp + j*Hv + hA) = *(float4*)oA;
            *(float4*)(etmp + j*Hv + hB) = *(float4*)oB;
        }
    }

    // ---- block reductions over r (16 partials per channel) ----
    // pass 1: agg -> x_new + x stats
    __syncthreads();
    #pragma unroll
    for (int q=0;q<4;q++){ sRed[r*128 + hA+q] = aggl[q]; sRed[r*128 + hB+q] = aggl[4+q]; }
    __syncthreads();
    if (tid < 128) {
        float t = 0.f;
        #pragma unroll
        for (int rr=0; rr<16; rr++) t += sRed[rr*128 + tid];
        float xv = g_unx[bi*Hv + tid] + t;
        g_xnew[bi*Hv + tid] = xv;
        atomicAdd(&g_xsum[tid], xv);
        atomicAdd(&g_xsumsq[tid], xv*xv);
    }
    // pass 2: e sum
    __syncthreads();
    #pragma unroll
    for (int q=0;q<4;q++){ sRed[r*128 + hA+q] = suml[q]; sRed[r*128 + hB+q] = suml[4+q]; }
    __syncthreads();
    if (tid < 128) {
        float t = 0.f;
        #pragma unroll
        for (int rr=0; rr<16; rr++) t += sRed[rr*128 + tid];
        atomicAdd(&g_esum[tid], t);
    }
    // pass 3: e sumsq
    __syncthreads();
    #pragma unroll
    for (int q=0;q<4;q++){ sRed[r*128 + hA+q] = sql[q]; sRed[r*128 + hB+q] = sql[4+q]; }
    __syncthreads();
    if (tid < 128) {
        float t = 0.f;
        #pragma unroll
        for (int rr=0; rr<16; rr++) t += sRed[rr*128 + tid];
        atomicAdd(&g_esumsq[tid], t);
    }
}

// K3: finalize BN scale/shift
__global__ void finalize_kernel(
    const float* __restrict__ bne_w, const float* __restrict__ bne_b,
    const float* __restrict__ bnn_w, const float* __restrict__ bnn_b)
{
    int h = threadIdx.x;
    if (h >= Hv) return;
    float cnt_e = (float)Bv * Nv * Nv;
    float m = g_esum[h] / cnt_e;
    float v = g_esumsq[h] / cnt_e - m*m;
    float s = bne_w[h] * rsqrtf(v + EPSv);
    g_escale[h] = s;
    g_eshift[h] = bne_b[h] - m*s;
    float cnt_x = (float)Bv * Nv;
    m = g_xsum[h] / cnt_x;
    v = g_xsumsq[h] / cnt_x - m*m;
    s = bnn_w[h] * rsqrtf(v + EPSv);
    g_xscale[h] = s;
    g_xshift[h] = bnn_b[h] - m*s;
}

// K4: out_x = x + relu(bn(x_new)) ; 65536 float4s
__global__ void x_out_kernel(const float* __restrict__ x, float* __restrict__ out)
{
    int idx = blockIdx.x * blockDim.x + threadIdx.x;   // float4 index
    if (idx >= X_ELEMS/4) return;
    int h4 = (idx & 31) * 4;
    float4 sc = *(const float4*)(g_xscale + h4);
    float4 sh = *(const float4*)(g_xshift + h4);
    float4 xn = *(const float4*)(g_xnew + idx*4);
    float4 xo = *(const float4*)(x + idx*4);
    float4 o;
    o.x = xo.x + fmaxf(0.f, xn.x*sc.x + sh.x);
    o.y = xo.y + fmaxf(0.f, xn.y*sc.y + sh.y);
    o.z = xo.z + fmaxf(0.f, xn.z*sc.z + sh.z);
    o.w = xo.w + fmaxf(0.f, xn.w*sc.w + sh.w);
    *(float4*)(out + idx*4) = o;
}

// K5: out_e = e + relu(bn(e_new)) ; 16777216 float4s
__global__ void e_out_kernel(const float* __restrict__ e, float* __restrict__ out)
{
    int idx = blockIdx.x * blockDim.x + threadIdx.x;   // float4 index
    int h4 = (idx & 31) * 4;
    float4 sc = *(const float4*)(g_escale + h4);
    float4 sh = *(const float4*)(g_eshift + h4);
    float4 en = *(const float4*)(g_e_tmp + (size_t)idx*4);
    float4 ev = *(const float4*)(e + (size_t)idx*4);
    float4 o;
    o.x = ev.x + fmaxf(0.f, en.x*sc.x + sh.x);
    o.y = ev.y + fmaxf(0.f, en.y*sc.y + sh.y);
    o.z = ev.z + fmaxf(0.f, en.z*sc.z + sh.z);
    o.w = ev.w + fmaxf(0.f, en.w*sc.w + sh.w);
    *(float4*)(out + (size_t)idx*4) = o;
}

extern "C" void kernel_launch(void* const* d_in, const int* in_sizes, int n_in,
                              void* d_out, int out_size)
{
    const float* x    = (const float*)d_in[0];
    const float* e    = (const float*)d_in[1];
    const float* Ue_w = (const float*)d_in[2];
    const float* Ue_b = (const float*)d_in[3];
    const float* Ve_w = (const float*)d_in[4];
    const float* Ve_b = (const float*)d_in[5];
    const float* Un_w = (const float*)d_in[6];
    const float* Un_b = (const float*)d_in[7];
    const float* Vn_w = (const float*)d_in[8];
    const float* Vn_b = (const float*)d_in[9];
    const float* bne_w = (const float*)d_in[10];
    const float* bne_b = (const float*)d_in[11];
    const float* bnn_w = (const float*)d_in[12];
    const float* bnn_b = (const float*)d_in[13];
    float* out = (float*)d_out;

    cudaFuncSetAttribute(node_linear_kernel,
        cudaFuncAttributeMaxDynamicSharedMemorySize, SMEM_BYTES);
    cudaFuncSetAttribute(edge_fused_kernel,
        cudaFuncAttributeMaxDynamicSharedMemorySize, SMEM_BYTES);

    zero_stats_kernel<<<1, 128>>>();

    dim3 g1(32, 3);
    node_linear_kernel<<<g1, 256, SMEM_BYTES>>>(x, Ve_w, Ve_b, Vn_w, Vn_b, Un_w, Un_b);

    edge_fused_kernel<<<Bv*Nv, 256, SMEM_BYTES>>>(e, Ue_w, Ue_b);

    finalize_kernel<<<1, 128>>>(bne_w, bne_b, bnn_w, bnn_b);

    x_out_kernel<<<(X_ELEMS/4 + 255)/256, 256>>>(x, out);

    e_out_kernel<<<E_ELEMS/4/256, 256>>>(e, out + X_ELEMS);
}

// round 7
// speedup vs baseline: 1.3996x; 1.3996x over previous
#include <cuda_runtime.h>
#include <cuda_bf16.h>
#include <cstdint>

#define Bv 8
#define Nv 256
#define Hv 128
#define EPSv 1e-5f
#define X_ELEMS (Bv*Nv*Hv)          /* 262144  */
#define E_ELEMS (Bv*Nv*Nv*Hv)       /* 67108864 */

// ---------------- scratch (static device globals) ----------------
__device__ float g_e_tmp[E_ELEMS];      // e_new (pre-BN), 256 MB
__device__ float g_vx[X_ELEMS];
__device__ float g_vnx[X_ELEMS];
__device__ float g_unx[X_ELEMS];
__device__ float g_xnew[X_ELEMS];
__device__ float g_esum[Hv];
__device__ float g_esumsq[Hv];
__device__ float g_xsum[Hv];
__device__ float g_xsumsq[Hv];
__device__ float g_escale[Hv];
__device__ float g_eshift[Hv];
__device__ float g_xscale[Hv];
__device__ float g_xshift[Hv];

// ================= mma.sync helpers (sm_80+, compiles for compute_103) =====
__device__ __forceinline__ uint32_t smem_u32(const void* p) {
    uint32_t a;
    asm("{ .reg .u64 t; cvta.to.shared.u64 t, %1; cvt.u32.u64 %0, t; }" : "=r"(a) : "l"(p));
    return a;
}
__device__ __forceinline__ void ldsm_x4(uint32_t* r, uint32_t a) {
    asm volatile("ldmatrix.sync.aligned.m8n8.x4.shared.b16 {%0,%1,%2,%3}, [%4];"
        : "=r"(r[0]), "=r"(r[1]), "=r"(r[2]), "=r"(r[3]) : "r"(a));
}
__device__ __forceinline__ void mma_bf16(float* c, const uint32_t* a, uint32_t b0, uint32_t b1) {
    asm volatile("mma.sync.aligned.m16n8k16.row.col.f32.bf16.bf16.f32 "
        "{%0,%1,%2,%3}, {%4,%5,%6,%7}, {%8,%9}, {%0,%1,%2,%3};"
        : "+f"(c[0]), "+f"(c[1]), "+f"(c[2]), "+f"(c[3])
        : "r"(a[0]), "r"(a[1]), "r"(a[2]), "r"(a[3]), "r"(b0), "r"(b1));
}

// split fp32 -> (hi, lo) bf16 pairs, packed 2-per-u32 (low address = low half)
__device__ __forceinline__ void split4(float4 v, uint2& hi, uint2& lo) {
    __nv_bfloat162 h01 = __floats2bfloat162_rn(v.x, v.y);
    __nv_bfloat162 h23 = __floats2bfloat162_rn(v.z, v.w);
    float2 f01 = __bfloat1622float2(h01);
    float2 f23 = __bfloat1622float2(h23);
    __nv_bfloat162 l01 = __floats2bfloat162_rn(v.x - f01.x, v.y - f01.y);
    __nv_bfloat162 l23 = __floats2bfloat162_rn(v.z - f23.x, v.w - f23.y);
    hi.x = *(uint32_t*)&h01; hi.y = *(uint32_t*)&h23;
    lo.x = *(uint32_t*)&l01; lo.y = *(uint32_t*)&l23;
}

// ---------------- edge kernel smem layout (bytes) ----------------
// W tiles [128 rows][136 bf16] pitch 272B; A tiles [64][136]
#define PITCHB 272
#define OFF_W_HI   0
#define OFF_W_LO   34816
#define OFF_A_HI   69632
#define OFF_A_LO   87040
#define OFF_BIAS   104448
#define OFF_ESUM   104960
#define OFF_ESQ    105472
#define OFF_AGG    105984
#define EDGE_SMEM  106496

// ================= K2: tensor-core fused edge kernel =================
// grid 2048 (one (b,i) per CTA), block 256 (8 warps: 2(m) x 4(n))
__global__ __launch_bounds__(256, 2) void edge_fused_mma_kernel(
    const float* __restrict__ e,
    const float* __restrict__ Ue_w, const float* __restrict__ Ue_b)
{
    extern __shared__ char smc[];
    uint32_t sbase = smem_u32(smc);
    int tid = threadIdx.x, lane = tid & 31, wid = tid >> 5;
    int bi = blockIdx.x, b = bi >> 8;

    float* biasS = (float*)(smc + OFF_BIAS);
    float* esumS = (float*)(smc + OFF_ESUM);
    float* esqS  = (float*)(smc + OFF_ESQ);
    float* aggS  = (float*)(smc + OFF_AGG);

    if (tid < 32) {
        float4 ub = *(const float4*)(Ue_b + tid * 4);
        float4 vx = *(const float4*)(g_vx + bi * Hv + tid * 4);
        *(float4*)(biasS + tid * 4) =
            make_float4(ub.x + vx.x, ub.y + vx.y, ub.z + vx.z, ub.w + vx.w);
    }
    if (tid < 128) { esumS[tid] = 0.f; esqS[tid] = 0.f; aggS[tid] = 0.f; }

    // ---- convert W -> hi/lo bf16 smem [h][k], k contiguous (= B col-major) ----
    {
        char* wh = smc + OFF_W_HI; char* wl = smc + OFF_W_LO;
        #pragma unroll
        for (int it = 0; it < 16; ++it) {
            int idx = it * 256 + tid;
            int r = idx >> 5, c = (idx & 31) * 4;
            uint2 hi, lo;
            split4(*(const float4*)(Ue_w + r * Hv + c), hi, lo);
            *(uint2*)(wh + r * PITCHB + c * 2) = hi;
            *(uint2*)(wl + r * PITCHB + c * 2) = lo;
        }
    }

    // warp tiling
    int wm = wid >> 2, wn = wid & 3;
    int m0 = wm * 32, n0 = wn * 32;

    // ldmatrix per-thread base addresses
    // A (x4 per m16 tile): row = m0 + mt*16 + (lane&15), kofs = (lane>>4)*8
    uint32_t aRow = (uint32_t)(lane & 15);
    uint32_t aK   = (uint32_t)((lane >> 4) * 8);
    uint32_t aHiBase0 = sbase + OFF_A_HI + (m0 + 0  + aRow) * PITCHB + aK * 2;
    uint32_t aHiBase1 = sbase + OFF_A_HI + (m0 + 16 + aRow) * PITCHB + aK * 2;
    uint32_t aLoBase0 = aHiBase0 + (OFF_A_LO - OFF_A_HI);
    uint32_t aLoBase1 = aHiBase1 + (OFF_A_LO - OFF_A_HI);
    // B (x4 covers 2 n8-tiles x k16): row = n0 + p*16 + ((lane>>4)<<3) + (lane&7),
    //                                 kofs = ((lane>>3)&1)*8
    uint32_t bRow = (uint32_t)(((lane >> 4) << 3) + (lane & 7));
    uint32_t bK   = (uint32_t)(((lane >> 3) & 1) * 8);
    uint32_t bHiBase0 = sbase + OFF_W_HI + (n0 + 0  + bRow) * PITCHB + bK * 2;
    uint32_t bHiBase1 = sbase + OFF_W_HI + (n0 + 16 + bRow) * PITCHB + bK * 2;
    uint32_t bLoBase0 = bHiBase0 + (OFF_W_LO - OFF_W_HI);
    uint32_t bLoBase1 = bHiBase1 + (OFF_W_LO - OFF_W_HI);

    const float* erow = e + (size_t)bi * Nv * Hv;
    float* etmp = g_e_tmp + (size_t)bi * Nv * Hv;

    float suml[8], sql[8], aggl[8];
    #pragma unroll
    for (int s = 0; s < 8; ++s) { suml[s] = 0.f; sql[s] = 0.f; aggl[s] = 0.f; }

    #pragma unroll 1
    for (int jt = 0; jt < 4; ++jt) {
        __syncthreads();   // previous tile's ldmatrix reads complete; W ready (jt=0)
        // ---- load + convert A j-tile (64 rows) ----
        {
            char* ah = smc + OFF_A_HI; char* al = smc + OFF_A_LO;
            const float* src = erow + (size_t)jt * 64 * Hv;
            #pragma unroll
            for (int it = 0; it < 8; ++it) {
                int idx = it * 256 + tid;
                int r = idx >> 5, c = (idx & 31) * 4;
                uint2 hi, lo;
                split4(*(const float4*)(src + r * Hv + c), hi, lo);
                *(uint2*)(ah + r * PITCHB + c * 2) = hi;
                *(uint2*)(al + r * PITCHB + c * 2) = lo;
            }
        }
        __syncthreads();

        // ---- mma mainloop: K = 8 steps of 16 ----
        float acc[2][4][4];
        #pragma unroll
        for (int mt = 0; mt < 2; ++mt)
            #pragma unroll
            for (int nt = 0; nt < 4; ++nt)
                #pragma unroll
                for (int q = 0; q < 4; ++q) acc[mt][nt][q] = 0.f;

        #pragma unroll
        for (int ks = 0; ks < 8; ++ks) {
            uint32_t ko = ks * 32;   // 16 bf16 = 32 bytes
            uint32_t ah[2][4], al[2][4], bh[2][4], bl[2][4];
            ldsm_x4(ah[0], aHiBase0 + ko);
            ldsm_x4(ah[1], aHiBase1 + ko);
            ldsm_x4(al[0], aLoBase0 + ko);
            ldsm_x4(al[1], aLoBase1 + ko);
            ldsm_x4(bh[0], bHiBase0 + ko);
            ldsm_x4(bh[1], bHiBase1 + ko);
            ldsm_x4(bl[0], bLoBase0 + ko);
            ldsm_x4(bl[1], bLoBase1 + ko);
            #pragma unroll
            for (int mt = 0; mt < 2; ++mt) {
                #pragma unroll
                for (int nt = 0; nt < 4; ++nt) {
                    uint32_t bh0 = bh[nt >> 1][(nt & 1) * 2], bh1 = bh[nt >> 1][(nt & 1) * 2 + 1];
                    uint32_t bl0 = bl[nt >> 1][(nt & 1) * 2], bl1 = bl[nt >> 1][(nt & 1) * 2 + 1];
                    mma_bf16(acc[mt][nt], ah[mt], bh0, bh1);   // hi*hi
                    mma_bf16(acc[mt][nt], ah[mt], bl0, bl1);   // hi*lo
                    mma_bf16(acc[mt][nt], al[mt], bh0, bh1);   // lo*hi
                }
            }
        }

        // ---- epilogue from registers ----
        #pragma unroll
        for (int mt = 0; mt < 2; ++mt) {
            #pragma unroll
            for (int half = 0; half < 2; ++half) {
                int row = m0 + mt * 16 + (lane >> 2) + half * 8;
                int j = jt * 64 + row;
                const float* vxj = g_vx  + (((b << 8) + j) << 7);
                const float* vnj = g_vnx + (((b << 8) + j) << 7);
                float* orow = etmp + ((size_t)j << 7);
                #pragma unroll
                for (int nt = 0; nt < 4; ++nt) {
                    int h = n0 + nt * 8 + 2 * (lane & 3);
                    float2 bs = *(float2*)(biasS + h);
                    float2 vx2 = *(const float2*)(vxj + h);
                    float2 vn2 = *(const float2*)(vnj + h);
                    float v0 = acc[mt][nt][half * 2 + 0] + bs.x + vx2.x;
                    float v1 = acc[mt][nt][half * 2 + 1] + bs.y + vx2.y;
                    float p0 = vn2.x / (1.f + __expf(-v0));
                    float p1 = vn2.y / (1.f + __expf(-v1));
                    int s = nt * 2;
                    suml[s] += v0;  suml[s + 1] += v1;
                    sql[s] += v0 * v0; sql[s + 1] += v1 * v1;
                    aggl[s] += p0;  aggl[s + 1] += p1;
                    *(float2*)(orow + h) = make_float2(v0, v1);
                }
            }
        }
    }

    // ---- reduce local sums: lanes sharing h are those differing in bits 2..4 ----
    #pragma unroll
    for (int s = 0; s < 8; ++s) {
        #pragma unroll
        for (int m = 4; m <= 16; m <<= 1) {
            suml[s] += __shfl_xor_sync(0xFFFFFFFF, suml[s], m);
            sql[s]  += __shfl_xor_sync(0xFFFFFFFF, sql[s],  m);
            aggl[s] += __shfl_xor_sync(0xFFFFFFFF, aggl[s], m);
        }
    }
    if (lane < 4) {
        #pragma unroll
        for (int s = 0; s < 8; ++s) {
            int h = n0 + (s >> 1) * 8 + 2 * lane + (s & 1);
            atomicAdd(&esumS[h], suml[s]);
            atomicAdd(&esqS[h],  sql[s]);
            atomicAdd(&aggS[h],  aggl[s]);
        }
    }
    __syncthreads();
    if (tid < 128) {
        float xv = g_unx[bi * Hv + tid] + aggS[tid];
        g_xnew[bi * Hv + tid] = xv;
        atomicAdd(&g_xsum[tid], xv);
        atomicAdd(&g_xsumsq[tid], xv * xv);
        atomicAdd(&g_esum[tid], esumS[tid]);
        atomicAdd(&g_esumsq[tid], esqS[tid]);
    }
}

// ================= node linears (fp32 SIMT, small) =================
#define SW_PITCH 132
#define SE_PITCH 132
#define NL_SMEM ((128*SW_PITCH + 64*SE_PITCH)*4)

#define GEMM_TILE(acc, sW, sE, r, hA, hB)                                   \
  {                                                                          \
    _Pragma("unroll")                                                        \
    for (int kk = 0; kk < 128; kk += 4) {                                    \
      float4 ev[4];                                                          \
      _Pragma("unroll")                                                      \
      for (int jj = 0; jj < 4; jj++)                                         \
        ev[jj] = *(const float4*)(sE + ((r)*4+jj)*SE_PITCH + kk);            \
      _Pragma("unroll")                                                      \
      for (int kq = 0; kq < 4; kq++) {                                       \
        float4 wa = *(const float4*)(sW + (kk+kq)*SW_PITCH + (hA));          \
        float4 wb = *(const float4*)(sW + (kk+kq)*SW_PITCH + (hB));          \
        _Pragma("unroll")                                                    \
        for (int jj = 0; jj < 4; jj++) {                                     \
          float ee = (kq==0)?ev[jj].x:(kq==1)?ev[jj].y:(kq==2)?ev[jj].z:ev[jj].w; \
          acc[jj][0] += ee*wa.x; acc[jj][1] += ee*wa.y;                      \
          acc[jj][2] += ee*wa.z; acc[jj][3] += ee*wa.w;                      \
          acc[jj][4] += ee*wb.x; acc[jj][5] += ee*wb.y;                      \
          acc[jj][6] += ee*wb.z; acc[jj][7] += ee*wb.w;                      \
        }                                                                    \
      }                                                                      \
    }                                                                        \
  }

__global__ void zero_stats_kernel() {
    int t = threadIdx.x;
    if (t < Hv) { g_esum[t]=0.f; g_esumsq[t]=0.f; g_xsum[t]=0.f; g_xsumsq[t]=0.f; }
}

__global__ __launch_bounds__(256, 2) void node_linear_kernel(
    const float* __restrict__ x,
    const float* __restrict__ Ve_w, const float* __restrict__ Ve_b,
    const float* __restrict__ Vn_w, const float* __restrict__ Vn_b,
    const float* __restrict__ Un_w, const float* __restrict__ Un_b)
{
    extern __shared__ float sm[];
    float* sW = sm;
    float* sE = sm + 128*SW_PITCH;
    int tid = threadIdx.x;
    int mat = blockIdx.y;
    const float* W    = (mat==0) ? Ve_w : (mat==1) ? Vn_w : Un_w;
    const float* bias = (mat==0) ? Ve_b : (mat==1) ? Vn_b : Un_b;
    float* out        = (mat==0) ? g_vx : (mat==1) ? g_vnx : g_unx;
    int row0 = blockIdx.x * 64;

    #pragma unroll 8
    for (int it = 0; it < 64; ++it) {
        int g = it*256 + tid;
        sW[(g & 127)*SW_PITCH + (g >> 7)] = W[g];
    }
    #pragma unroll
    for (int it = 0; it < 8; ++it) {
        int idx = it*256 + tid;
        int rr = idx >> 5, kk = (idx & 31)*4;
        *(float4*)(sE + rr*SE_PITCH + kk) = *(const float4*)(x + (row0+rr)*Hv + kk);
    }
    __syncthreads();

    int c = tid & 15, r = tid >> 4;
    int hA = c*4, hB = 64 + c*4;
    float acc[4][8];
    #pragma unroll
    for (int jj=0;jj<4;jj++)
        #pragma unroll
        for (int q=0;q<8;q++) acc[jj][q]=0.f;

    GEMM_TILE(acc, sW, sE, r, hA, hB);

    float bA[4], bB[4];
    #pragma unroll
    for (int q=0;q<4;q++){ bA[q]=bias[hA+q]; bB[q]=bias[hB+q]; }
    #pragma unroll
    for (int jj=0;jj<4;jj++){
        int rw = row0 + r*4 + jj;
        float oA[4], oB[4];
        #pragma unroll
        for (int q=0;q<4;q++){ oA[q]=acc[jj][q]+bA[q]; oB[q]=acc[jj][4+q]+bB[q]; }
        *(float4*)(out + rw*Hv + hA) = *(float4*)oA;
        *(float4*)(out + rw*Hv + hB) = *(float4*)oB;
    }
}

__global__ void finalize_kernel(
    const float* __restrict__ bne_w, const float* __restrict__ bne_b,
    const float* __restrict__ bnn_w, const float* __restrict__ bnn_b)
{
    int h = threadIdx.x;
    if (h >= Hv) return;
    float cnt_e = (float)Bv * Nv * Nv;
    float m = g_esum[h] / cnt_e;
    float v = g_esumsq[h] / cnt_e - m*m;
    float s = bne_w[h] * rsqrtf(v + EPSv);
    g_escale[h] = s;
    g_eshift[h] = bne_b[h] - m*s;
    float cnt_x = (float)Bv * Nv;
    m = g_xsum[h] / cnt_x;
    v = g_xsumsq[h] / cnt_x - m*m;
    s = bnn_w[h] * rsqrtf(v + EPSv);
    g_xscale[h] = s;
    g_xshift[h] = bnn_b[h] - m*s;
}

__global__ void x_out_kernel(const float* __restrict__ x, float* __restrict__ out)
{
    int idx = blockIdx.x * blockDim.x + threadIdx.x;
    if (idx >= X_ELEMS/4) return;
    int h4 = (idx & 31) * 4;
    float4 sc = *(const float4*)(g_xscale + h4);
    float4 sh = *(const float4*)(g_xshift + h4);
    float4 xn = *(const float4*)(g_xnew + idx*4);
    float4 xo = *(const float4*)(x + idx*4);
    float4 o;
    o.x = xo.x + fmaxf(0.f, xn.x*sc.x + sh.x);
    o.y = xo.y + fmaxf(0.f, xn.y*sc.y + sh.y);
    o.z = xo.z + fmaxf(0.f, xn.z*sc.z + sh.z);
    o.w = xo.w + fmaxf(0.f, xn.w*sc.w + sh.w);
    *(float4*)(out + idx*4) = o;
}

__global__ void e_out_kernel(const float* __restrict__ e, float* __restrict__ out)
{
    int idx = blockIdx.x * blockDim.x + threadIdx.x;
    int h4 = (idx & 31) * 4;
    float4 sc = *(const float4*)(g_escale + h4);
    float4 sh = *(const float4*)(g_eshift + h4);
    float4 en = *(const float4*)(g_e_tmp + (size_t)idx*4);
    float4 ev = *(const float4*)(e + (size_t)idx*4);
    float4 o;
    o.x = ev.x + fmaxf(0.f, en.x*sc.x + sh.x);
    o.y = ev.y + fmaxf(0.f, en.y*sc.y + sh.y);
    o.z = ev.z + fmaxf(0.f, en.z*sc.z + sh.z);
    o.w = ev.w + fmaxf(0.f, en.w*sc.w + sh.w);
    *(float4*)(out + (size_t)idx*4) = o;
}

extern "C" void kernel_launch(void* const* d_in, const int* in_sizes, int n_in,
                              void* d_out, int out_size)
{
    const float* x    = (const float*)d_in[0];
    const float* e    = (const float*)d_in[1];
    const float* Ue_w = (const float*)d_in[2];
    const float* Ue_b = (const float*)d_in[3];
    const float* Ve_w = (const float*)d_in[4];
    const float* Ve_b = (const float*)d_in[5];
    const float* Un_w = (const float*)d_in[6];
    const float* Un_b = (const float*)d_in[7];
    const float* Vn_w = (const float*)d_in[8];
    const float* Vn_b = (const float*)d_in[9];
    const float* bne_w = (const float*)d_in[10];
    const float* bne_b = (const float*)d_in[11];
    const float* bnn_w = (const float*)d_in[12];
    const float* bnn_b = (const float*)d_in[13];
    float* out = (float*)d_out;

    cudaFuncSetAttribute(node_linear_kernel,
        cudaFuncAttributeMaxDynamicSharedMemorySize, NL_SMEM);
    cudaFuncSetAttribute(edge_fused_mma_kernel,
        cudaFuncAttributeMaxDynamicSharedMemorySize, EDGE_SMEM);

    zero_stats_kernel<<<1, 128>>>();

    node_linear_kernel<<<dim3(32, 3), 256, NL_SMEM>>>(x, Ve_w, Ve_b, Vn_w, Vn_b, Un_w, Un_b);

    edge_fused_mma_kernel<<<Bv*Nv, 256, EDGE_SMEM>>>(e, Ue_w, Ue_b);

    finalize_kernel<<<1, 128>>>(bne_w, bne_b, bnn_w, bnn_b);

    x_out_kernel<<<(X_ELEMS/4 + 255)/256, 256>>>(x, out);

    e_out_kernel<<<E_ELEMS/4/256, 256>>>(e, out + X_ELEMS);
}

// round 10
// speedup vs baseline: 1.4841x; 1.0604x over previous
#include <cuda_runtime.h>
#include <cuda_bf16.h>
#include <cstdint>

#define Bv 8
#define Nv 256
#define Hv 128
#define EPSv 1e-5f
#define X_ELEMS (Bv*Nv*Hv)          /* 262144  */
#define E_ELEMS (Bv*Nv*Nv*Hv)       /* 67108864 */

// ---------------- scratch (static device globals) ----------------
__device__ float g_e_tmp[E_ELEMS];      // e_new (pre-BN), 256 MB
__device__ float g_vx[X_ELEMS];
__device__ float g_vnx[X_ELEMS];
__device__ float g_unx[X_ELEMS];
__device__ float g_xnew[X_ELEMS];
__device__ float g_esum[Hv];
__device__ float g_esumsq[Hv];
__device__ float g_xsum[Hv];
__device__ float g_xsumsq[Hv];
__device__ float g_escale[Hv];
__device__ float g_eshift[Hv];
__device__ float g_xscale[Hv];
__device__ float g_xshift[Hv];

// ================= mma.sync helpers (sm_80+, compiles for compute_103) =====
__device__ __forceinline__ uint32_t smem_u32(const void* p) {
    uint32_t a;
    asm("{ .reg .u64 t; cvta.to.shared.u64 t, %1; cvt.u32.u64 %0, t; }" : "=r"(a) : "l"(p));
    return a;
}
__device__ __forceinline__ void ldsm_x4(uint32_t* r, uint32_t a) {
    asm volatile("ldmatrix.sync.aligned.m8n8.x4.shared.b16 {%0,%1,%2,%3}, [%4];"
        : "=r"(r[0]), "=r"(r[1]), "=r"(r[2]), "=r"(r[3]) : "r"(a));
}
__device__ __forceinline__ void mma_bf16(float* c, const uint32_t* a, uint32_t b0, uint32_t b1) {
    asm volatile("mma.sync.aligned.m16n8k16.row.col.f32.bf16.bf16.f32 "
        "{%0,%1,%2,%3}, {%4,%5,%6,%7}, {%8,%9}, {%0,%1,%2,%3};"
        : "+f"(c[0]), "+f"(c[1]), "+f"(c[2]), "+f"(c[3])
        : "r"(a[0]), "r"(a[1]), "r"(a[2]), "r"(a[3]), "r"(b0), "r"(b1));
}

// split fp32 -> (hi, lo) bf16 pairs, packed 2-per-u32 (low address = low half)
__device__ __forceinline__ void split4(float4 v, uint2& hi, uint2& lo) {
    __nv_bfloat162 h01 = __floats2bfloat162_rn(v.x, v.y);
    __nv_bfloat162 h23 = __floats2bfloat162_rn(v.z, v.w);
    float2 f01 = __bfloat1622float2(h01);
    float2 f23 = __bfloat1622float2(h23);
    __nv_bfloat162 l01 = __floats2bfloat162_rn(v.x - f01.x, v.y - f01.y);
    __nv_bfloat162 l23 = __floats2bfloat162_rn(v.z - f23.x, v.w - f23.y);
    hi.x = *(uint32_t*)&h01; hi.y = *(uint32_t*)&h23;
    lo.x = *(uint32_t*)&l01; lo.y = *(uint32_t*)&l23;
}

// ---------------- edge kernel smem layout (bytes) ----------------
// W tiles [128 rows][136 bf16] pitch 272B; A tiles [64][136]
#define PITCHB 272
#define OFF_W_HI   0
#define OFF_W_LO   34816
#define OFF_A_HI   69632
#define OFF_A_LO   87040
#define OFF_BIAS   104448
#define OFF_ESUM   104960
#define OFF_ESQ    105472
#define OFF_AGG    105984
#define EDGE_SMEM  106496

// ================= K2: tensor-core fused edge kernel =================
// grid 2048 (one (b,i) per CTA), block 256 (8 warps: 2(m) x 4(n))
__global__ __launch_bounds__(256, 2) void edge_fused_mma_kernel(
    const float* __restrict__ e,
    const float* __restrict__ Ue_w, const float* __restrict__ Ue_b)
{
    extern __shared__ char smc[];
    uint32_t sbase = smem_u32(smc);
    int tid = threadIdx.x, lane = tid & 31, wid = tid >> 5;
    int bi = blockIdx.x, b = bi >> 8;

    float* biasS = (float*)(smc + OFF_BIAS);
    float* esumS = (float*)(smc + OFF_ESUM);
    float* esqS  = (float*)(smc + OFF_ESQ);
    float* aggS  = (float*)(smc + OFF_AGG);

    if (tid < 32) {
        float4 ub = *(const float4*)(Ue_b + tid * 4);
        float4 vx = *(const float4*)(g_vx + bi * Hv + tid * 4);
        *(float4*)(biasS + tid * 4) =
            make_float4(ub.x + vx.x, ub.y + vx.y, ub.z + vx.z, ub.w + vx.w);
    }
    if (tid < 128) { esumS[tid] = 0.f; esqS[tid] = 0.f; aggS[tid] = 0.f; }

    // ---- convert W -> hi/lo bf16 smem [h][k], k contiguous (= B col-major) ----
    {
        char* wh = smc + OFF_W_HI; char* wl = smc + OFF_W_LO;
        #pragma unroll
        for (int it = 0; it < 16; ++it) {
            int idx = it * 256 + tid;
            int r = idx >> 5, c = (idx & 31) * 4;
            uint2 hi, lo;
            split4(*(const float4*)(Ue_w + r * Hv + c), hi, lo);
            *(uint2*)(wh + r * PITCHB + c * 2) = hi;
            *(uint2*)(wl + r * PITCHB + c * 2) = lo;
        }
    }

    // warp tiling
    int wm = wid >> 2, wn = wid & 3;
    int m0 = wm * 32, n0 = wn * 32;

    // ldmatrix per-thread base addresses
    uint32_t aRow = (uint32_t)(lane & 15);
    uint32_t aK   = (uint32_t)((lane >> 4) * 8);
    uint32_t aHiBase0 = sbase + OFF_A_HI + (m0 + 0  + aRow) * PITCHB + aK * 2;
    uint32_t aHiBase1 = sbase + OFF_A_HI + (m0 + 16 + aRow) * PITCHB + aK * 2;
    uint32_t aLoBase0 = aHiBase0 + (OFF_A_LO - OFF_A_HI);
    uint32_t aLoBase1 = aHiBase1 + (OFF_A_LO - OFF_A_HI);
    uint32_t bRow = (uint32_t)(((lane >> 4) << 3) + (lane & 7));
    uint32_t bK   = (uint32_t)(((lane >> 3) & 1) * 8);
    uint32_t bHiBase0 = sbase + OFF_W_HI + (n0 + 0  + bRow) * PITCHB + bK * 2;
    uint32_t bHiBase1 = sbase + OFF_W_HI + (n0 + 16 + bRow) * PITCHB + bK * 2;
    uint32_t bLoBase0 = bHiBase0 + (OFF_W_LO - OFF_W_HI);
    uint32_t bLoBase1 = bHiBase1 + (OFF_W_LO - OFF_W_HI);

    const float* erow = e + (size_t)bi * Nv * Hv;
    float* etmp = g_e_tmp + (size_t)bi * Nv * Hv;

    float suml[8], sql[8], aggl[8];
    #pragma unroll
    for (int s = 0; s < 8; ++s) { suml[s] = 0.f; sql[s] = 0.f; aggl[s] = 0.f; }

    // per-thread fixed coords for A load/convert
    int ldR = tid >> 5, ldC = (tid & 31) * 4;

    #pragma unroll 1
    for (int jt = 0; jt < 4; ++jt) {
        // ---- front-batched gmem loads: issue all 8 LDG.128 before the barrier ----
        float4 pf[8];
        {
            const float* src = erow + (size_t)jt * 64 * Hv + ldR * Hv + ldC;
            #pragma unroll
            for (int it = 0; it < 8; ++it)
                pf[it] = *(const float4*)(src + it * 8 * Hv);
        }
        __syncthreads();   // previous tile's ldmatrix reads complete; W ready (jt=0)
        {
            char* ah = smc + OFF_A_HI; char* al = smc + OFF_A_LO;
            #pragma unroll
            for (int it = 0; it < 8; ++it) {
                int r = ldR + it * 8;
                uint2 hi, lo;
                split4(pf[it], hi, lo);
                *(uint2*)(ah + r * PITCHB + ldC * 2) = hi;
                *(uint2*)(al + r * PITCHB + ldC * 2) = lo;
            }
        }
        __syncthreads();

        // ---- mma mainloop: K = 8 steps of 16 ----
        float acc[2][4][4];
        #pragma unroll
        for (int mt = 0; mt < 2; ++mt)
            #pragma unroll
            for (int nt = 0; nt < 4; ++nt)
                #pragma unroll
                for (int q = 0; q < 4; ++q) acc[mt][nt][q] = 0.f;

        #pragma unroll
        for (int ks = 0; ks < 8; ++ks) {
            uint32_t ko = ks * 32;   // 16 bf16 = 32 bytes
            uint32_t ah[2][4], al[2][4], bh[2][4], bl[2][4];
            ldsm_x4(ah[0], aHiBase0 + ko);
            ldsm_x4(ah[1], aHiBase1 + ko);
            ldsm_x4(al[0], aLoBase0 + ko);
            ldsm_x4(al[1], aLoBase1 + ko);
            ldsm_x4(bh[0], bHiBase0 + ko);
            ldsm_x4(bh[1], bHiBase1 + ko);
            ldsm_x4(bl[0], bLoBase0 + ko);
            ldsm_x4(bl[1], bLoBase1 + ko);
            #pragma unroll
            for (int mt = 0; mt < 2; ++mt) {
                #pragma unroll
                for (int nt = 0; nt < 4; ++nt) {
                    uint32_t bh0 = bh[nt >> 1][(nt & 1) * 2], bh1 = bh[nt >> 1][(nt & 1) * 2 + 1];
                    uint32_t bl0 = bl[nt >> 1][(nt & 1) * 2], bl1 = bl[nt >> 1][(nt & 1) * 2 + 1];
                    mma_bf16(acc[mt][nt], ah[mt], bh0, bh1);   // hi*hi
                    mma_bf16(acc[mt][nt], ah[mt], bl0, bl1);   // hi*lo
                    mma_bf16(acc[mt][nt], al[mt], bh0, bh1);   // lo*hi
                }
            }
        }

        // ---- epilogue from registers ----
        #pragma unroll
        for (int mt = 0; mt < 2; ++mt) {
            #pragma unroll
            for (int half = 0; half < 2; ++half) {
                int row = m0 + mt * 16 + (lane >> 2) + half * 8;
                int j = jt * 64 + row;
                const float* vxj = g_vx  + (((b << 8) + j) << 7);
                const float* vnj = g_vnx + (((b << 8) + j) << 7);
                float* orow = etmp + ((size_t)j << 7);
                #pragma unroll
                for (int nt = 0; nt < 4; ++nt) {
                    int h = n0 + nt * 8 + 2 * (lane & 3);
                    float2 bs = *(float2*)(biasS + h);
                    float2 vx2 = *(const float2*)(vxj + h);
                    float2 vn2 = *(const float2*)(vnj + h);
                    float v0 = acc[mt][nt][half * 2 + 0] + bs.x + vx2.x;
                    float v1 = acc[mt][nt][half * 2 + 1] + bs.y + vx2.y;
                    float p0 = __fdividef(vn2.x, 1.f + __expf(-v0));
                    float p1 = __fdividef(vn2.y, 1.f + __expf(-v1));
                    int s = nt * 2;
                    suml[s] += v0;  suml[s + 1] += v1;
                    sql[s] += v0 * v0; sql[s + 1] += v1 * v1;
                    aggl[s] += p0;  aggl[s + 1] += p1;
                    *(float2*)(orow + h) = make_float2(v0, v1);
                }
            }
        }
    }

    // ---- reduce local sums: lanes sharing h are those differing in bits 2..4 ----
    #pragma unroll
    for (int s = 0; s < 8; ++s) {
        #pragma unroll
        for (int m = 4; m <= 16; m <<= 1) {
            suml[s] += __shfl_xor_sync(0xFFFFFFFF, suml[s], m);
            sql[s]  += __shfl_xor_sync(0xFFFFFFFF, sql[s],  m);
            aggl[s] += __shfl_xor_sync(0xFFFFFFFF, aggl[s], m);
        }
    }
    if (lane < 4) {
        #pragma unroll
        for (int s = 0; s < 8; ++s) {
            int h = n0 + (s >> 1) * 8 + 2 * lane + (s & 1);
            atomicAdd(&esumS[h], suml[s]);
            atomicAdd(&esqS[h],  sql[s]);
            atomicAdd(&aggS[h],  aggl[s]);
        }
    }
    __syncthreads();
    if (tid < 128) {
        float xv = g_unx[bi * Hv + tid] + aggS[tid];
        g_xnew[bi * Hv + tid] = xv;
        atomicAdd(&g_xsum[tid], xv);
        atomicAdd(&g_xsumsq[tid], xv * xv);
        atomicAdd(&g_esum[tid], esumS[tid]);
        atomicAdd(&g_esumsq[tid], esqS[tid]);
    }
}

// ================= node linears (fp32 SIMT, small) =================
#define SW_PITCH 132
#define SE_PITCH 132
#define NL_SMEM ((128*SW_PITCH + 64*SE_PITCH)*4)

#define GEMM_TILE(acc, sW, sE, r, hA, hB)                                   \
  {                                                                          \
    _Pragma("unroll")                                                        \
    for (int kk = 0; kk < 128; kk += 4) {                                    \
      float4 ev[4];                                                          \
      _Pragma("unroll")                                                      \
      for (int jj = 0; jj < 4; jj++)                                         \
        ev[jj] = *(const float4*)(sE + ((r)*4+jj)*SE_PITCH + kk);            \
      _Pragma("unroll")                                                      \
      for (int kq = 0; kq < 4; kq++) {                                       \
        float4 wa = *(const float4*)(sW + (kk+kq)*SW_PITCH + (hA));          \
        float4 wb = *(const float4*)(sW + (kk+kq)*SW_PITCH + (hB));          \
        _Pragma("unroll")                                                    \
        for (int jj = 0; jj < 4; jj++) {                                     \
          float ee = (kq==0)?ev[jj].x:(kq==1)?ev[jj].y:(kq==2)?ev[jj].z:ev[jj].w; \
          acc[jj][0] += ee*wa.x; acc[jj][1] += ee*wa.y;                      \
          acc[jj][2] += ee*wa.z; acc[jj][3] += ee*wa.w;                      \
          acc[jj][4] += ee*wb.x; acc[jj][5] += ee*wb.y;                      \
          acc[jj][6] += ee*wb.z; acc[jj][7] += ee*wb.w;                      \
        }                                                                    \
      }                                                                      \
    }                                                                        \
  }

__global__ __launch_bounds__(256, 2) void node_linear_kernel(
    const float* __restrict__ x,
    const float* __restrict__ Ve_w, const float* __restrict__ Ve_b,
    const float* __restrict__ Vn_w, const float* __restrict__ Vn_b,
    const float* __restrict__ Un_w, const float* __restrict__ Un_b)
{
    extern __shared__ float sm[];
    float* sW = sm;
    float* sE = sm + 128*SW_PITCH;
    int tid = threadIdx.x;
    int mat = blockIdx.y;

    // folded zero_stats (independent of this kernel's outputs; completes
    // before edge_fused_mma_kernel launch boundary)
    if (blockIdx.x == 0 && mat == 0 && tid < 128) {
        g_esum[tid] = 0.f; g_esumsq[tid] = 0.f;
        g_xsum[tid] = 0.f; g_xsumsq[tid] = 0.f;
    }

    const float* W    = (mat==0) ? Ve_w : (mat==1) ? Vn_w : Un_w;
    const float* bias = (mat==0) ? Ve_b : (mat==1) ? Vn_b : Un_b;
    float* out        = (mat==0) ? g_vx : (mat==1) ? g_vnx : g_unx;
    int row0 = blockIdx.x * 64;

    #pragma unroll 8
    for (int it = 0; it < 64; ++it) {
        int g = it*256 + tid;
        sW[(g & 127)*SW_PITCH + (g >> 7)] = W[g];
    }
    #pragma unroll
    for (int it = 0; it < 8; ++it) {
        int idx = it*256 + tid;
        int rr = idx >> 5, kk = (idx & 31)*4;
        *(float4*)(sE + rr*SE_PITCH + kk) = *(const float4*)(x + (row0+rr)*Hv + kk);
    }
    __syncthreads();

    int c = tid & 15, r = tid >> 4;
    int hA = c*4, hB = 64 + c*4;
    float acc[4][8];
    #pragma unroll
    for (int jj=0;jj<4;jj++)
        #pragma unroll
        for (int q=0;q<8;q++) acc[jj][q]=0.f;

    GEMM_TILE(acc, sW, sE, r, hA, hB);

    float bA[4], bB[4];
    #pragma unroll
    for (int q=0;q<4;q++){ bA[q]=bias[hA+q]; bB[q]=bias[hB+q]; }
    #pragma unroll
    for (int jj=0;jj<4;jj++){
        int rw = row0 + r*4 + jj;
        float oA[4], oB[4];
        #pragma unroll
        for (int q=0;q<4;q++){ oA[q]=acc[jj][q]+bA[q]; oB[q]=acc[jj][4+q]+bB[q]; }
        *(float4*)(out + rw*Hv + hA) = *(float4*)oA;
        *(float4*)(out + rw*Hv + hB) = *(float4*)oB;
    }
}

__global__ void finalize_kernel(
    const float* __restrict__ bne_w, const float* __restrict__ bne_b,
    const float* __restrict__ bnn_w, const float* __restrict__ bnn_b)
{
    int h = threadIdx.x;
    if (h >= Hv) return;
    float cnt_e = (float)Bv * Nv * Nv;
    float m = g_esum[h] / cnt_e;
    float v = g_esumsq[h] / cnt_e - m*m;
    float s = bne_w[h] * rsqrtf(v + EPSv);
    g_escale[h] = s;
    g_eshift[h] = bne_b[h] - m*s;
    float cnt_x = (float)Bv * Nv;
    m = g_xsum[h] / cnt_x;
    v = g_xsumsq[h] / cnt_x - m*m;
    s = bnn_w[h] * rsqrtf(v + EPSv);
    g_xscale[h] = s;
    g_xshift[h] = bnn_b[h] - m*s;
}

__global__ void x_out_kernel(const float* __restrict__ x, float* __restrict__ out)
{
    int idx = blockIdx.x * blockDim.x + threadIdx.x;
    if (idx >= X_ELEMS/4) return;
    int h4 = (idx & 31) * 4;
    float4 sc = *(const float4*)(g_xscale + h4);
    float4 sh = *(const float4*)(g_xshift + h4);
    float4 xn = *(const float4*)(g_xnew + idx*4);
    float4 xo = *(const float4*)(x + idx*4);
    float4 o;
    o.x = xo.x + fmaxf(0.f, xn.x*sc.x + sh.x);
    o.y = xo.y + fmaxf(0.f, xn.y*sc.y + sh.y);
    o.z = xo.z + fmaxf(0.f, xn.z*sc.z + sh.z);
    o.w = xo.w + fmaxf(0.f, xn.w*sc.w + sh.w);
    *(float4*)(out + idx*4) = o;
}

// 2 float4 per thread, streaming (evict-first) hints
__global__ __launch_bounds__(256) void e_out_kernel(const float* __restrict__ e, float* __restrict__ out)
{
    size_t base = (size_t)blockIdx.x * 512 + threadIdx.x;
    #pragma unroll
    for (int rep = 0; rep < 2; ++rep) {
        size_t idx = base + rep * 256;          // float4 index
        int h4 = ((int)idx & 31) * 4;
        float4 sc = *(const float4*)(g_escale + h4);
        float4 sh = *(const float4*)(g_eshift + h4);
        float4 en = __ldcs((const float4*)(g_e_tmp) + idx);
        float4 ev = __ldcs((const float4*)(e) + idx);
        float4 o;
        o.x = ev.x + fmaxf(0.f, en.x*sc.x + sh.x);
        o.y = ev.y + fmaxf(0.f, en.y*sc.y + sh.y);
        o.z = ev.z + fmaxf(0.f, en.z*sc.z + sh.z);
        o.w = ev.w + fmaxf(0.f, en.w*sc.w + sh.w);
        __stcs((float4*)(out) + idx, o);
    }
}

extern "C" void kernel_launch(void* const* d_in, const int* in_sizes, int n_in,
                              void* d_out, int out_size)
{
    const float* x    = (const float*)d_in[0];
    const float* e    = (const float*)d_in[1];
    const float* Ue_w = (const float*)d_in[2];
    const float* Ue_b = (const float*)d_in[3];
    const float* Ve_w = (const float*)d_in[4];
    const float* Ve_b = (const float*)d_in[5];
    const float* Un_w = (const float*)d_in[6];
    const float* Un_b = (const float*)d_in[7];
    const float* Vn_w = (const float*)d_in[8];
    const float* Vn_b = (const float*)d_in[9];
    const float* bne_w = (const float*)d_in[10];
    const float* bne_b = (const float*)d_in[11];
    const float* bnn_w = (const float*)d_in[12];
    const float* bnn_b = (const float*)d_in[13];
    float* out = (float*)d_out;

    cudaFuncSetAttribute(node_linear_kernel,
        cudaFuncAttributeMaxDynamicSharedMemorySize, NL_SMEM);
    cudaFuncSetAttribute(edge_fused_mma_kernel,
        cudaFuncAttributeMaxDynamicSharedMemorySize, EDGE_SMEM);

    node_linear_kernel<<<dim3(32, 3), 256, NL_SMEM>>>(x, Ve_w, Ve_b, Vn_w, Vn_b, Un_w, Un_b);

    edge_fused_mma_kernel<<<Bv*Nv, 256, EDGE_SMEM>>>(e, Ue_w, Ue_b);

    finalize_kernel<<<1, 128>>>(bne_w, bne_b, bnn_w, bnn_b);

    x_out_kernel<<<(X_ELEMS/4 + 255)/256, 256>>>(x, out);

    e_out_kernel<<<E_ELEMS/4/512, 256>>>(e, out + X_ELEMS);
}

// round 11
// speedup vs baseline: 1.6896x; 1.1385x over previous
#include <cuda_runtime.h>
#include <cuda_fp16.h>
#include <cstdint>

#define Bv 8
#define Nv 256
#define Hv 128
#define EPSv 1e-5f
#define X_ELEMS (Bv*Nv*Hv)          /* 262144  */
#define E_ELEMS (Bv*Nv*Nv*Hv)       /* 67108864 */

// ---------------- scratch (static device globals) ----------------
__device__ float g_e_tmp[E_ELEMS];      // e_new (pre-BN), 256 MB
__device__ float g_vx[X_ELEMS];
__device__ float g_vnx[X_ELEMS];
__device__ float g_unx[X_ELEMS];
__device__ float g_xnew[X_ELEMS];
__device__ float g_esum[Hv];
__device__ float g_esumsq[Hv];
__device__ float g_xsum[Hv];
__device__ float g_xsumsq[Hv];
__device__ float g_escale[Hv];
__device__ float g_eshift[Hv];
__device__ float g_xscale[Hv];
__device__ float g_xshift[Hv];

// ================= mma.sync helpers (sm_80+, compiles for compute_103) =====
__device__ __forceinline__ uint32_t smem_u32(const void* p) {
    uint32_t a;
    asm("{ .reg .u64 t; cvta.to.shared.u64 t, %1; cvt.u32.u64 %0, t; }" : "=r"(a) : "l"(p));
    return a;
}
__device__ __forceinline__ void ldsm_x4(uint32_t* r, uint32_t a) {
    asm volatile("ldmatrix.sync.aligned.m8n8.x4.shared.b16 {%0,%1,%2,%3}, [%4];"
        : "=r"(r[0]), "=r"(r[1]), "=r"(r[2]), "=r"(r[3]) : "r"(a));
}
__device__ __forceinline__ void mma_f16(float* c, const uint32_t* a, uint32_t b0, uint32_t b1) {
    asm volatile("mma.sync.aligned.m16n8k16.row.col.f32.f16.f16.f32 "
        "{%0,%1,%2,%3}, {%4,%5,%6,%7}, {%8,%9}, {%0,%1,%2,%3};"
        : "+f"(c[0]), "+f"(c[1]), "+f"(c[2]), "+f"(c[3])
        : "r"(a[0]), "r"(a[1]), "r"(a[2]), "r"(a[3]), "r"(b0), "r"(b1));
}

// split fp32 -> (hi, lo) fp16 pairs, packed 2-per-u32 (low address = low half)
__device__ __forceinline__ void split4h(float4 v, uint2& hi, uint2& lo) {
    __half2 h01 = __floats2half2_rn(v.x, v.y);
    __half2 h23 = __floats2half2_rn(v.z, v.w);
    float2 f01 = __half22float2(h01);
    float2 f23 = __half22float2(h23);
    __half2 l01 = __floats2half2_rn(v.x - f01.x, v.y - f01.y);
    __half2 l23 = __floats2half2_rn(v.z - f23.x, v.w - f23.y);
    hi.x = *(uint32_t*)&h01; hi.y = *(uint32_t*)&h23;
    lo.x = *(uint32_t*)&l01; lo.y = *(uint32_t*)&l23;
}
// fp32 -> fp16 (hi only), packed
__device__ __forceinline__ uint2 cvt4h(float4 v) {
    __half2 h01 = __floats2half2_rn(v.x, v.y);
    __half2 h23 = __floats2half2_rn(v.z, v.w);
    uint2 r; r.x = *(uint32_t*)&h01; r.y = *(uint32_t*)&h23;
    return r;
}

// ---------------- edge kernel smem layout (bytes) ----------------
// W tile [128 rows][136 fp16] pitch 272B; A tiles [64][136]
#define PITCHB 272
#define OFF_W_HI   0        /* 34816 */
#define OFF_A_HI   34816    /* 17408 */
#define OFF_A_LO   52224    /* 17408 */
#define OFF_BIAS   69632    /* 512 */
#define OFF_ESUM   70144
#define OFF_ESQ    70656
#define OFF_AGG    71168
#define EDGE_SMEM  71680

// ================= K2: tensor-core fused edge kernel =================
// grid 2048 (one (b,i) per CTA), block 256 (8 warps: 2(m) x 4(n))
// D = e @ W^T via fp16 2-MMA split: e_hi*W_hi + e_lo*W_hi (W_lo term ~2^-12, dropped)
__global__ __launch_bounds__(256, 2) void edge_fused_mma_kernel(
    const float* __restrict__ e,
    const float* __restrict__ Ue_w, const float* __restrict__ Ue_b)
{
    extern __shared__ char smc[];
    uint32_t sbase = smem_u32(smc);
    int tid = threadIdx.x, lane = tid & 31, wid = tid >> 5;
    int bi = blockIdx.x, b = bi >> 8;

    float* biasS = (float*)(smc + OFF_BIAS);
    float* esumS = (float*)(smc + OFF_ESUM);
    float* esqS  = (float*)(smc + OFF_ESQ);
    float* aggS  = (float*)(smc + OFF_AGG);

    if (tid < 32) {
        float4 ub = *(const float4*)(Ue_b + tid * 4);
        float4 vx = *(const float4*)(g_vx + bi * Hv + tid * 4);
        *(float4*)(biasS + tid * 4) =
            make_float4(ub.x + vx.x, ub.y + vx.y, ub.z + vx.z, ub.w + vx.w);
    }
    if (tid < 128) { esumS[tid] = 0.f; esqS[tid] = 0.f; aggS[tid] = 0.f; }

    // ---- convert W -> fp16 smem [h][k], k contiguous (= B col-major) ----
    {
        char* wh = smc + OFF_W_HI;
        #pragma unroll
        for (int it = 0; it < 16; ++it) {
            int idx = it * 256 + tid;
            int r = idx >> 5, c = (idx & 31) * 4;
            *(uint2*)(wh + r * PITCHB + c * 2) = cvt4h(*(const float4*)(Ue_w + r * Hv + c));
        }
    }

    // warp tiling
    int wm = wid >> 2, wn = wid & 3;
    int m0 = wm * 32, n0 = wn * 32;

    // ldmatrix per-thread base addresses
    uint32_t aRow = (uint32_t)(lane & 15);
    uint32_t aK   = (uint32_t)((lane >> 4) * 8);
    uint32_t aHiBase0 = sbase + OFF_A_HI + (m0 + 0  + aRow) * PITCHB + aK * 2;
    uint32_t aHiBase1 = sbase + OFF_A_HI + (m0 + 16 + aRow) * PITCHB + aK * 2;
    uint32_t aLoBase0 = aHiBase0 + (OFF_A_LO - OFF_A_HI);
    uint32_t aLoBase1 = aHiBase1 + (OFF_A_LO - OFF_A_HI);
    uint32_t bRow = (uint32_t)(((lane >> 4) << 3) + (lane & 7));
    uint32_t bK   = (uint32_t)(((lane >> 3) & 1) * 8);
    uint32_t bHiBase0 = sbase + OFF_W_HI + (n0 + 0  + bRow) * PITCHB + bK * 2;
    uint32_t bHiBase1 = sbase + OFF_W_HI + (n0 + 16 + bRow) * PITCHB + bK * 2;

    const float* erow = e + (size_t)bi * Nv * Hv;
    float* etmp = g_e_tmp + (size_t)bi * Nv * Hv;

    float suml[8], sql[8], aggl[8];
    #pragma unroll
    for (int s = 0; s < 8; ++s) { suml[s] = 0.f; sql[s] = 0.f; aggl[s] = 0.f; }

    // per-thread fixed coords for A load/convert
    int ldR = tid >> 5, ldC = (tid & 31) * 4;

    #pragma unroll 1
    for (int jt = 0; jt < 4; ++jt) {
        // ---- front-batched gmem loads: issue all 8 LDG.128 before the barrier ----
        float4 pf[8];
        {
            const float* src = erow + (size_t)jt * 64 * Hv + ldR * Hv + ldC;
            #pragma unroll
            for (int it = 0; it < 8; ++it)
                pf[it] = *(const float4*)(src + it * 8 * Hv);
        }
        __syncthreads();   // previous tile's ldmatrix reads complete; W ready (jt=0)
        {
            char* ah = smc + OFF_A_HI; char* al = smc + OFF_A_LO;
            #pragma unroll
            for (int it = 0; it < 8; ++it) {
                int r = ldR + it * 8;
                uint2 hi, lo;
                split4h(pf[it], hi, lo);
                *(uint2*)(ah + r * PITCHB + ldC * 2) = hi;
                *(uint2*)(al + r * PITCHB + ldC * 2) = lo;
            }
        }
        __syncthreads();

        // ---- mma mainloop: K = 8 steps of 16 ----
        float acc[2][4][4];
        #pragma unroll
        for (int mt = 0; mt < 2; ++mt)
            #pragma unroll
            for (int nt = 0; nt < 4; ++nt)
                #pragma unroll
                for (int q = 0; q < 4; ++q) acc[mt][nt][q] = 0.f;

        #pragma unroll
        for (int ks = 0; ks < 8; ++ks) {
            uint32_t ko = ks * 32;   // 16 fp16 = 32 bytes
            uint32_t ah[2][4], al[2][4], bh[2][4];
            ldsm_x4(ah[0], aHiBase0 + ko);
            ldsm_x4(ah[1], aHiBase1 + ko);
            ldsm_x4(al[0], aLoBase0 + ko);
            ldsm_x4(al[1], aLoBase1 + ko);
            ldsm_x4(bh[0], bHiBase0 + ko);
            ldsm_x4(bh[1], bHiBase1 + ko);
            #pragma unroll
            for (int mt = 0; mt < 2; ++mt) {
                #pragma unroll
                for (int nt = 0; nt < 4; ++nt) {
                    uint32_t bh0 = bh[nt >> 1][(nt & 1) * 2], bh1 = bh[nt >> 1][(nt & 1) * 2 + 1];
                    mma_f16(acc[mt][nt], ah[mt], bh0, bh1);   // e_hi * W_hi
                    mma_f16(acc[mt][nt], al[mt], bh0, bh1);   // e_lo * W_hi
                }
            }
        }

        // ---- epilogue from registers ----
        #pragma unroll
        for (int mt = 0; mt < 2; ++mt) {
            #pragma unroll
            for (int half = 0; half < 2; ++half) {
                int row = m0 + mt * 16 + (lane >> 2) + half * 8;
                int j = jt * 64 + row;
                const float* vxj = g_vx  + (((b << 8) + j) << 7);
                const float* vnj = g_vnx + (((b << 8) + j) << 7);
                float* orow = etmp + ((size_t)j << 7);
                #pragma unroll
                for (int nt = 0; nt < 4; ++nt) {
                    int h = n0 + nt * 8 + 2 * (lane & 3);
                    float2 bs = *(float2*)(biasS + h);
                    float2 vx2 = *(const float2*)(vxj + h);
                    float2 vn2 = *(const float2*)(vnj + h);
                    float v0 = acc[mt][nt][half * 2 + 0] + bs.x + vx2.x;
                    float v1 = acc[mt][nt][half * 2 + 1] + bs.y + vx2.y;
                    float p0 = __fdividef(vn2.x, 1.f + __expf(-v0));
                    float p1 = __fdividef(vn2.y, 1.f + __expf(-v1));
                    int s = nt * 2;
                    suml[s] += v0;  suml[s + 1] += v1;
                    sql[s] += v0 * v0; sql[s + 1] += v1 * v1;
                    aggl[s] += p0;  aggl[s + 1] += p1;
                    *(float2*)(orow + h) = make_float2(v0, v1);
                }
            }
        }
    }

    // ---- reduce local sums: lanes sharing h are those differing in bits 2..4 ----
    #pragma unroll
    for (int s = 0; s < 8; ++s) {
        #pragma unroll
        for (int m = 4; m <= 16; m <<= 1) {
            suml[s] += __shfl_xor_sync(0xFFFFFFFF, suml[s], m);
            sql[s]  += __shfl_xor_sync(0xFFFFFFFF, sql[s],  m);
            aggl[s] += __shfl_xor_sync(0xFFFFFFFF, aggl[s], m);
        }
    }
    if (lane < 4) {
        #pragma unroll
        for (int s = 0; s < 8; ++s) {
            int h = n0 + (s >> 1) * 8 + 2 * lane + (s & 1);
            atomicAdd(&esumS[h], suml[s]);
            atomicAdd(&esqS[h],  sql[s]);
            atomicAdd(&aggS[h],  aggl[s]);
        }
    }
    __syncthreads();
    if (tid < 128) {
        float xv = g_unx[bi * Hv + tid] + aggS[tid];
        g_xnew[bi * Hv + tid] = xv;
        atomicAdd(&g_xsum[tid], xv);
        atomicAdd(&g_xsumsq[tid], xv * xv);
        atomicAdd(&g_esum[tid], esumS[tid]);
        atomicAdd(&g_esumsq[tid], esqS[tid]);
    }
}

// ================= node linears (fp32 SIMT, small) =================
#define SW_PITCH 132
#define SE_PITCH 132
#define NL_SMEM ((128*SW_PITCH + 64*SE_PITCH)*4)

#define GEMM_TILE(acc, sW, sE, r, hA, hB)                                   \
  {                                                                          \
    _Pragma("unroll")                                                        \
    for (int kk = 0; kk < 128; kk += 4) {                                    \
      float4 ev[4];                                                          \
      _Pragma("unroll")                                                      \
      for (int jj = 0; jj < 4; jj++)                                         \
        ev[jj] = *(const float4*)(sE + ((r)*4+jj)*SE_PITCH + kk);            \
      _Pragma("unroll")                                                      \
      for (int kq = 0; kq < 4; kq++) {                                       \
        float4 wa = *(const float4*)(sW + (kk+kq)*SW_PITCH + (hA));          \
        float4 wb = *(const float4*)(sW + (kk+kq)*SW_PITCH + (hB));          \
        _Pragma("unroll")                                                    \
        for (int jj = 0; jj < 4; jj++) {                                     \
          float ee = (kq==0)?ev[jj].x:(kq==1)?ev[jj].y:(kq==2)?ev[jj].z:ev[jj].w; \
          acc[jj][0] += ee*wa.x; acc[jj][1] += ee*wa.y;                      \
          acc[jj][2] += ee*wa.z; acc[jj][3] += ee*wa.w;                      \
          acc[jj][4] += ee*wb.x; acc[jj][5] += ee*wb.y;                      \
          acc[jj][6] += ee*wb.z; acc[jj][7] += ee*wb.w;                      \
        }                                                                    \
      }                                                                      \
    }                                                                        \
  }

__global__ __launch_bounds__(256, 2) void node_linear_kernel(
    const float* __restrict__ x,
    const float* __restrict__ Ve_w, const float* __restrict__ Ve_b,
    const float* __restrict__ Vn_w, const float* __restrict__ Vn_b,
    const float* __restrict__ Un_w, const float* __restrict__ Un_b)
{
    extern __shared__ float sm[];
    float* sW = sm;
    float* sE = sm + 128*SW_PITCH;
    int tid = threadIdx.x;
    int mat = blockIdx.y;

    // folded zero_stats (independent of this kernel's outputs; completes
    // before edge_fused_mma_kernel launch boundary)
    if (blockIdx.x == 0 && mat == 0 && tid < 128) {
        g_esum[tid] = 0.f; g_esumsq[tid] = 0.f;
        g_xsum[tid] = 0.f; g_xsumsq[tid] = 0.f;
    }

    const float* W    = (mat==0) ? Ve_w : (mat==1) ? Vn_w : Un_w;
    const float* bias = (mat==0) ? Ve_b : (mat==1) ? Vn_b : Un_b;
    float* out        = (mat==0) ? g_vx : (mat==1) ? g_vnx : g_unx;
    int row0 = blockIdx.x * 64;

    #pragma unroll 8
    for (int it = 0; it < 64; ++it) {
        int g = it*256 + tid;
        sW[(g & 127)*SW_PITCH + (g >> 7)] = W[g];
    }
    #pragma unroll
    for (int it = 0; it < 8; ++it) {
        int idx = it*256 + tid;
        int rr = idx >> 5, kk = (idx & 31)*4;
        *(float4*)(sE + rr*SE_PITCH + kk) = *(const float4*)(x + (row0+rr)*Hv + kk);
    }
    __syncthreads();

    int c = tid & 15, r = tid >> 4;
    int hA = c*4, hB = 64 + c*4;
    float acc[4][8];
    #pragma unroll
    for (int jj=0;jj<4;jj++)
        #pragma unroll
        for (int q=0;q<8;q++) acc[jj][q]=0.f;

    GEMM_TILE(acc, sW, sE, r, hA, hB);

    float bA[4], bB[4];
    #pragma unroll
    for (int q=0;q<4;q++){ bA[q]=bias[hA+q]; bB[q]=bias[hB+q]; }
    #pragma unroll
    for (int jj=0;jj<4;jj++){
        int rw = row0 + r*4 + jj;
        float oA[4], oB[4];
        #pragma unroll
        for (int q=0;q<4;q++){ oA[q]=acc[jj][q]+bA[q]; oB[q]=acc[jj][4+q]+bB[q]; }
        *(float4*)(out + rw*Hv + hA) = *(float4*)oA;
        *(float4*)(out + rw*Hv + hB) = *(float4*)oB;
    }
}

__global__ void finalize_kernel(
    const float* __restrict__ bne_w, const float* __restrict__ bne_b,
    const float* __restrict__ bnn_w, const float* __restrict__ bnn_b)
{
    int h = threadIdx.x;
    if (h >= Hv) return;
    float cnt_e = (float)Bv * Nv * Nv;
    float m = g_esum[h] / cnt_e;
    float v = g_esumsq[h] / cnt_e - m*m;
    float s = bne_w[h] * rsqrtf(v + EPSv);
    g_escale[h] = s;
    g_eshift[h] = bne_b[h] - m*s;
    float cnt_x = (float)Bv * Nv;
    m = g_xsum[h] / cnt_x;
    v = g_xsumsq[h] / cnt_x - m*m;
    s = bnn_w[h] * rsqrtf(v + EPSv);
    g_xscale[h] = s;
    g_xshift[h] = bnn_b[h] - m*s;
}

__global__ void x_out_kernel(const float* __restrict__ x, float* __restrict__ out)
{
    int idx = blockIdx.x * blockDim.x + threadIdx.x;
    if (idx >= X_ELEMS/4) return;
    int h4 = (idx & 31) * 4;
    float4 sc = *(const float4*)(g_xscale + h4);
    float4 sh = *(const float4*)(g_xshift + h4);
    float4 xn = *(const float4*)(g_xnew + idx*4);
    float4 xo = *(const float4*)(x + idx*4);
    float4 o;
    o.x = xo.x + fmaxf(0.f, xn.x*sc.x + sh.x);
    o.y = xo.y + fmaxf(0.f, xn.y*sc.y + sh.y);
    o.z = xo.z + fmaxf(0.f, xn.z*sc.z + sh.z);
    o.w = xo.w + fmaxf(0.f, xn.w*sc.w + sh.w);
    *(float4*)(out + idx*4) = o;
}

// 2 float4 per thread, streaming (evict-first) hints
__global__ __launch_bounds__(256) void e_out_kernel(const float* __restrict__ e, float* __restrict__ out)
{
    size_t base = (size_t)blockIdx.x * 512 + threadIdx.x;
    #pragma unroll
    for (int rep = 0; rep < 2; ++rep) {
        size_t idx = base + rep * 256;          // float4 index
        int h4 = ((int)idx & 31) * 4;
        float4 sc = *(const float4*)(g_escale + h4);
        float4 sh = *(const float4*)(g_eshift + h4);
        float4 en = __ldcs((const float4*)(g_e_tmp) + idx);
        float4 ev = __ldcs((const float4*)(e) + idx);
        float4 o;
        o.x = ev.x + fmaxf(0.f, en.x*sc.x + sh.x);
        o.y = ev.y + fmaxf(0.f, en.y*sc.y + sh.y);
        o.z = ev.z + fmaxf(0.f, en.z*sc.z + sh.z);
        o.w = ev.w + fmaxf(0.f, en.w*sc.w + sh.w);
        __stcs((float4*)(out) + idx, o);
    }
}

extern "C" void kernel_launch(void* const* d_in, const int* in_sizes, int n_in,
                              void* d_out, int out_size)
{
    const float* x    = (const float*)d_in[0];
    const float* e    = (const float*)d_in[1];
    const float* Ue_w = (const float*)d_in[2];
    const float* Ue_b = (const float*)d_in[3];
    const float* Ve_w = (const float*)d_in[4];
    const float* Ve_b = (const float*)d_in[5];
    const float* Un_w = (const float*)d_in[6];
    const float* Un_b = (const float*)d_in[7];
    const float* Vn_w = (const float*)d_in[8];
    const float* Vn_b = (const float*)d_in[9];
    const float* bne_w = (const float*)d_in[10];
    const float* bne_b = (const float*)d_in[11];
    const float* bnn_w = (const float*)d_in[12];
    const float* bnn_b = (const float*)d_in[13];
    float* out = (float*)d_out;

    cudaFuncSetAttribute(node_linear_kernel,
        cudaFuncAttributeMaxDynamicSharedMemorySize, NL_SMEM);
    cudaFuncSetAttribute(edge_fused_mma_kernel,
        cudaFuncAttributeMaxDynamicSharedMemorySize, EDGE_SMEM);

    node_linear_kernel<<<dim3(32, 3), 256, NL_SMEM>>>(x, Ve_w, Ve_b, Vn_w, Vn_b, Un_w, Un_b);

    edge_fused_mma_kernel<<<Bv*Nv, 256, EDGE_SMEM>>>(e, Ue_w, Ue_b);

    finalize_kernel<<<1, 128>>>(bne_w, bne_b, bnn_w, bnn_b);

    x_out_kernel<<<(X_ELEMS/4 + 255)/256, 256>>>(x, out);

    e_out_kernel<<<E_ELEMS/4/512, 256>>>(e, out + X_ELEMS);
}

// round 12
// speedup vs baseline: 1.7941x; 1.0618x over previous
#include <cuda_runtime.h>
#include <cuda_fp16.h>
#include <cstdint>

#define Bv 8
#define Nv 256
#define Hv 128
#define EPSv 1e-5f
#define X_ELEMS (Bv*Nv*Hv)          /* 262144  */
#define E_ELEMS (Bv*Nv*Nv*Hv)       /* 67108864 */

// ---------------- scratch (static device globals) ----------------
__device__ __half g_e_tmp[E_ELEMS];     // e_new (pre-BN), fp16, 128 MB
__device__ float g_vx[X_ELEMS];
__device__ float g_vnx[X_ELEMS];
__device__ float g_unx[X_ELEMS];
__device__ float g_xnew[X_ELEMS];
__device__ float g_esum[Hv];
__device__ float g_esumsq[Hv];
__device__ float g_xsum[Hv];
__device__ float g_xsumsq[Hv];
__device__ float g_escale[Hv];
__device__ float g_eshift[Hv];
__device__ float g_xscale[Hv];
__device__ float g_xshift[Hv];

// ================= mma.sync helpers (sm_80+, compiles for compute_103) =====
__device__ __forceinline__ uint32_t smem_u32(const void* p) {
    uint32_t a;
    asm("{ .reg .u64 t; cvta.to.shared.u64 t, %1; cvt.u32.u64 %0, t; }" : "=r"(a) : "l"(p));
    return a;
}
__device__ __forceinline__ void ldsm_x4(uint32_t* r, uint32_t a) {
    asm volatile("ldmatrix.sync.aligned.m8n8.x4.shared.b16 {%0,%1,%2,%3}, [%4];"
        : "=r"(r[0]), "=r"(r[1]), "=r"(r[2]), "=r"(r[3]) : "r"(a));
}
__device__ __forceinline__ void mma_f16(float* c, const uint32_t* a, uint32_t b0, uint32_t b1) {
    asm volatile("mma.sync.aligned.m16n8k16.row.col.f32.f16.f16.f32 "
        "{%0,%1,%2,%3}, {%4,%5,%6,%7}, {%8,%9}, {%0,%1,%2,%3};"
        : "+f"(c[0]), "+f"(c[1]), "+f"(c[2]), "+f"(c[3])
        : "r"(a[0]), "r"(a[1]), "r"(a[2]), "r"(a[3]), "r"(b0), "r"(b1));
}

// split fp32 -> (hi, lo) fp16 pairs, packed 2-per-u32 (low address = low half)
__device__ __forceinline__ void split4h(float4 v, uint2& hi, uint2& lo) {
    __half2 h01 = __floats2half2_rn(v.x, v.y);
    __half2 h23 = __floats2half2_rn(v.z, v.w);
    float2 f01 = __half22float2(h01);
    float2 f23 = __half22float2(h23);
    __half2 l01 = __floats2half2_rn(v.x - f01.x, v.y - f01.y);
    __half2 l23 = __floats2half2_rn(v.z - f23.x, v.w - f23.y);
    hi.x = *(uint32_t*)&h01; hi.y = *(uint32_t*)&h23;
    lo.x = *(uint32_t*)&l01; lo.y = *(uint32_t*)&l23;
}
// fp32 -> fp16 (hi only), packed
__device__ __forceinline__ uint2 cvt4h(float4 v) {
    __half2 h01 = __floats2half2_rn(v.x, v.y);
    __half2 h23 = __floats2half2_rn(v.z, v.w);
    uint2 r; r.x = *(uint32_t*)&h01; r.y = *(uint32_t*)&h23;
    return r;
}

// ---------------- edge kernel smem layout (bytes) ----------------
// W tile [128 rows][136 fp16] pitch 272B; A tiles [64][136]
#define PITCHB 272
#define OFF_W_HI   0        /* 34816 */
#define OFF_A_HI   34816    /* 17408 */
#define OFF_A_LO   52224    /* 17408 */
#define OFF_BIAS   69632    /* 512 */
#define OFF_ESUM   70144
#define OFF_ESQ    70656
#define OFF_AGG    71168
#define EDGE_SMEM  71680

// ================= K2: tensor-core fused edge kernel =================
// grid 2048 (one (b,i) per CTA), block 256 (8 warps: 2(m) x 4(n))
// D = e @ W^T via fp16 2-MMA split: e_hi*W_hi + e_lo*W_hi (W_lo term ~2^-12, dropped)
__global__ __launch_bounds__(256, 2) void edge_fused_mma_kernel(
    const float* __restrict__ e,
    const float* __restrict__ Ue_w, const float* __restrict__ Ue_b)
{
    extern __shared__ char smc[];
    uint32_t sbase = smem_u32(smc);
    int tid = threadIdx.x, lane = tid & 31, wid = tid >> 5;
    int bi = blockIdx.x, b = bi >> 8;

    float* biasS = (float*)(smc + OFF_BIAS);
    float* esumS = (float*)(smc + OFF_ESUM);
    float* esqS  = (float*)(smc + OFF_ESQ);
    float* aggS  = (float*)(smc + OFF_AGG);

    if (tid < 32) {
        float4 ub = *(const float4*)(Ue_b + tid * 4);
        float4 vx = *(const float4*)(g_vx + bi * Hv + tid * 4);
        *(float4*)(biasS + tid * 4) =
            make_float4(ub.x + vx.x, ub.y + vx.y, ub.z + vx.z, ub.w + vx.w);
    }
    if (tid < 128) { esumS[tid] = 0.f; esqS[tid] = 0.f; aggS[tid] = 0.f; }

    // ---- convert W -> fp16 smem [h][k], k contiguous (= B col-major) ----
    {
        char* wh = smc + OFF_W_HI;
        #pragma unroll
        for (int it = 0; it < 16; ++it) {
            int idx = it * 256 + tid;
            int r = idx >> 5, c = (idx & 31) * 4;
            *(uint2*)(wh + r * PITCHB + c * 2) = cvt4h(*(const float4*)(Ue_w + r * Hv + c));
        }
    }

    // warp tiling
    int wm = wid >> 2, wn = wid & 3;
    int m0 = wm * 32, n0 = wn * 32;

    // ldmatrix per-thread base addresses
    uint32_t aRow = (uint32_t)(lane & 15);
    uint32_t aK   = (uint32_t)((lane >> 4) * 8);
    uint32_t aHiBase0 = sbase + OFF_A_HI + (m0 + 0  + aRow) * PITCHB + aK * 2;
    uint32_t aHiBase1 = sbase + OFF_A_HI + (m0 + 16 + aRow) * PITCHB + aK * 2;
    uint32_t aLoBase0 = aHiBase0 + (OFF_A_LO - OFF_A_HI);
    uint32_t aLoBase1 = aHiBase1 + (OFF_A_LO - OFF_A_HI);
    uint32_t bRow = (uint32_t)(((lane >> 4) << 3) + (lane & 7));
    uint32_t bK   = (uint32_t)(((lane >> 3) & 1) * 8);
    uint32_t bHiBase0 = sbase + OFF_W_HI + (n0 + 0  + bRow) * PITCHB + bK * 2;
    uint32_t bHiBase1 = sbase + OFF_W_HI + (n0 + 16 + bRow) * PITCHB + bK * 2;

    const float* erow = e + (size_t)bi * Nv * Hv;
    __half* etmp = g_e_tmp + (size_t)bi * Nv * Hv;

    float suml[8], sql[8], aggl[8];
    #pragma unroll
    for (int s = 0; s < 8; ++s) { suml[s] = 0.f; sql[s] = 0.f; aggl[s] = 0.f; }

    // per-thread fixed coords for A load/convert
    int ldR = tid >> 5, ldC = (tid & 31) * 4;

    #pragma unroll 1
    for (int jt = 0; jt < 4; ++jt) {
        // ---- front-batched gmem loads: issue all 8 LDG.128 before the barrier ----
        float4 pf[8];
        {
            const float* src = erow + (size_t)jt * 64 * Hv + ldR * Hv + ldC;
            #pragma unroll
            for (int it = 0; it < 8; ++it)
                pf[it] = *(const float4*)(src + it * 8 * Hv);
        }
        __syncthreads();   // previous tile's ldmatrix reads complete; W ready (jt=0)
        {
            char* ah = smc + OFF_A_HI; char* al = smc + OFF_A_LO;
            #pragma unroll
            for (int it = 0; it < 8; ++it) {
                int r = ldR + it * 8;
                uint2 hi, lo;
                split4h(pf[it], hi, lo);
                *(uint2*)(ah + r * PITCHB + ldC * 2) = hi;
                *(uint2*)(al + r * PITCHB + ldC * 2) = lo;
            }
        }
        __syncthreads();

        // ---- mma mainloop: K = 8 steps of 16 ----
        float acc[2][4][4];
        #pragma unroll
        for (int mt = 0; mt < 2; ++mt)
            #pragma unroll
            for (int nt = 0; nt < 4; ++nt)
                #pragma unroll
                for (int q = 0; q < 4; ++q) acc[mt][nt][q] = 0.f;

        #pragma unroll
        for (int ks = 0; ks < 8; ++ks) {
            uint32_t ko = ks * 32;   // 16 fp16 = 32 bytes
            uint32_t ah[2][4], al[2][4], bh[2][4];
            ldsm_x4(ah[0], aHiBase0 + ko);
            ldsm_x4(ah[1], aHiBase1 + ko);
            ldsm_x4(al[0], aLoBase0 + ko);
            ldsm_x4(al[1], aLoBase1 + ko);
            ldsm_x4(bh[0], bHiBase0 + ko);
            ldsm_x4(bh[1], bHiBase1 + ko);
            #pragma unroll
            for (int mt = 0; mt < 2; ++mt) {
                #pragma unroll
                for (int nt = 0; nt < 4; ++nt) {
                    uint32_t bh0 = bh[nt >> 1][(nt & 1) * 2], bh1 = bh[nt >> 1][(nt & 1) * 2 + 1];
                    mma_f16(acc[mt][nt], ah[mt], bh0, bh1);   // e_hi * W_hi
                    mma_f16(acc[mt][nt], al[mt], bh0, bh1);   // e_lo * W_hi
                }
            }
        }

        // ---- epilogue from registers (e_new stored as fp16) ----
        #pragma unroll
        for (int mt = 0; mt < 2; ++mt) {
            #pragma unroll
            for (int half = 0; half < 2; ++half) {
                int row = m0 + mt * 16 + (lane >> 2) + half * 8;
                int j = jt * 64 + row;
                const float* vxj = g_vx  + (((b << 8) + j) << 7);
                const float* vnj = g_vnx + (((b << 8) + j) << 7);
                __half* orow = etmp + ((size_t)j << 7);
                #pragma unroll
                for (int nt = 0; nt < 4; ++nt) {
                    int h = n0 + nt * 8 + 2 * (lane & 3);
                    float2 bs = *(float2*)(biasS + h);
                    float2 vx2 = *(const float2*)(vxj + h);
                    float2 vn2 = *(const float2*)(vnj + h);
                    float v0 = acc[mt][nt][half * 2 + 0] + bs.x + vx2.x;
                    float v1 = acc[mt][nt][half * 2 + 1] + bs.y + vx2.y;
                    float p0 = __fdividef(vn2.x, 1.f + __expf(-v0));
                    float p1 = __fdividef(vn2.y, 1.f + __expf(-v1));
                    int s = nt * 2;
                    suml[s] += v0;  suml[s + 1] += v1;
                    sql[s] += v0 * v0; sql[s + 1] += v1 * v1;
                    aggl[s] += p0;  aggl[s + 1] += p1;
                    *(__half2*)(orow + h) = __floats2half2_rn(v0, v1);
                }
            }
        }
    }

    // ---- reduce local sums: lanes sharing h are those differing in bits 2..4 ----
    #pragma unroll
    for (int s = 0; s < 8; ++s) {
        #pragma unroll
        for (int m = 4; m <= 16; m <<= 1) {
            suml[s] += __shfl_xor_sync(0xFFFFFFFF, suml[s], m);
            sql[s]  += __shfl_xor_sync(0xFFFFFFFF, sql[s],  m);
            aggl[s] += __shfl_xor_sync(0xFFFFFFFF, aggl[s], m);
        }
    }
    if (lane < 4) {
        #pragma unroll
        for (int s = 0; s < 8; ++s) {
            int h = n0 + (s >> 1) * 8 + 2 * lane + (s & 1);
            atomicAdd(&esumS[h], suml[s]);
            atomicAdd(&esqS[h],  sql[s]);
            atomicAdd(&aggS[h],  aggl[s]);
        }
    }
    __syncthreads();
    if (tid < 128) {
        float xv = g_unx[bi * Hv + tid] + aggS[tid];
        g_xnew[bi * Hv + tid] = xv;
        atomicAdd(&g_xsum[tid], xv);
        atomicAdd(&g_xsumsq[tid], xv * xv);
        atomicAdd(&g_esum[tid], esumS[tid]);
        atomicAdd(&g_esumsq[tid], esqS[tid]);
    }
}

// ================= node linears (fp32 SIMT, small) =================
#define SW_PITCH 132
#define SE_PITCH 132
#define NL_SMEM ((128*SW_PITCH + 64*SE_PITCH)*4)

#define GEMM_TILE(acc, sW, sE, r, hA, hB)                                   \
  {                                                                          \
    _Pragma("unroll")                                                        \
    for (int kk = 0; kk < 128; kk += 4) {                                    \
      float4 ev[4];                                                          \
      _Pragma("unroll")                                                      \
      for (int jj = 0; jj < 4; jj++)                                         \
        ev[jj] = *(const float4*)(sE + ((r)*4+jj)*SE_PITCH + kk);            \
      _Pragma("unroll")                                                      \
      for (int kq = 0; kq < 4; kq++) {                                       \
        float4 wa = *(const float4*)(sW + (kk+kq)*SW_PITCH + (hA));          \
        float4 wb = *(const float4*)(sW + (kk+kq)*SW_PITCH + (hB));          \
        _Pragma("unroll")                                                    \
        for (int jj = 0; jj < 4; jj++) {                                     \
          float ee = (kq==0)?ev[jj].x:(kq==1)?ev[jj].y:(kq==2)?ev[jj].z:ev[jj].w; \
          acc[jj][0] += ee*wa.x; acc[jj][1] += ee*wa.y;                      \
          acc[jj][2] += ee*wa.z; acc[jj][3] += ee*wa.w;                      \
          acc[jj][4] += ee*wb.x; acc[jj][5] += ee*wb.y;                      \
          acc[jj][6] += ee*wb.z; acc[jj][7] += ee*wb.w;                      \
        }                                                                    \
      }                                                                      \
    }                                                                        \
  }

__global__ __launch_bounds__(256, 2) void node_linear_kernel(
    const float* __restrict__ x,
    const float* __restrict__ Ve_w, const float* __restrict__ Ve_b,
    const float* __restrict__ Vn_w, const float* __restrict__ Vn_b,
    const float* __restrict__ Un_w, const float* __restrict__ Un_b)
{
    extern __shared__ float sm[];
    float* sW = sm;
    float* sE = sm + 128*SW_PITCH;
    int tid = threadIdx.x;
    int mat = blockIdx.y;

    // folded zero_stats (independent of this kernel's outputs; completes
    // before edge_fused_mma_kernel launch boundary)
    if (blockIdx.x == 0 && mat == 0 && tid < 128) {
        g_esum[tid] = 0.f; g_esumsq[tid] = 0.f;
        g_xsum[tid] = 0.f; g_xsumsq[tid] = 0.f;
    }

    const float* W    = (mat==0) ? Ve_w : (mat==1) ? Vn_w : Un_w;
    const float* bias = (mat==0) ? Ve_b : (mat==1) ? Vn_b : Un_b;
    float* out        = (mat==0) ? g_vx : (mat==1) ? g_vnx : g_unx;
    int row0 = blockIdx.x * 64;

    #pragma unroll 8
    for (int it = 0; it < 64; ++it) {
        int g = it*256 + tid;
        sW[(g & 127)*SW_PITCH + (g >> 7)] = W[g];
    }
    #pragma unroll
    for (int it = 0; it < 8; ++it) {
        int idx = it*256 + tid;
        int rr = idx >> 5, kk = (idx & 31)*4;
        *(float4*)(sE + rr*SE_PITCH + kk) = *(const float4*)(x + (row0+rr)*Hv + kk);
    }
    __syncthreads();

    int c = tid & 15, r = tid >> 4;
    int hA = c*4, hB = 64 + c*4;
    float acc[4][8];
    #pragma unroll
    for (int jj=0;jj<4;jj++)
        #pragma unroll
        for (int q=0;q<8;q++) acc[jj][q]=0.f;

    GEMM_TILE(acc, sW, sE, r, hA, hB);

    float bA[4], bB[4];
    #pragma unroll
    for (int q=0;q<4;q++){ bA[q]=bias[hA+q]; bB[q]=bias[hB+q]; }
    #pragma unroll
    for (int jj=0;jj<4;jj++){
        int rw = row0 + r*4 + jj;
        float oA[4], oB[4];
        #pragma unroll
        for (int q=0;q<4;q++){ oA[q]=acc[jj][q]+bA[q]; oB[q]=acc[jj][4+q]+bB[q]; }
        *(float4*)(out + rw*Hv + hA) = *(float4*)oA;
        *(float4*)(out + rw*Hv + hB) = *(float4*)oB;
    }
}

__global__ void finalize_kernel(
    const float* __restrict__ bne_w, const float* __restrict__ bne_b,
    const float* __restrict__ bnn_w, const float* __restrict__ bnn_b)
{
    int h = threadIdx.x;
    if (h >= Hv) return;
    float cnt_e = (float)Bv * Nv * Nv;
    float m = g_esum[h] / cnt_e;
    float v = g_esumsq[h] / cnt_e - m*m;
    float s = bne_w[h] * rsqrtf(v + EPSv);
    g_escale[h] = s;
    g_eshift[h] = bne_b[h] - m*s;
    float cnt_x = (float)Bv * Nv;
    m = g_xsum[h] / cnt_x;
    v = g_xsumsq[h] / cnt_x - m*m;
    s = bnn_w[h] * rsqrtf(v + EPSv);
    g_xscale[h] = s;
    g_xshift[h] = bnn_b[h] - m*s;
}

__global__ void x_out_kernel(const float* __restrict__ x, float* __restrict__ out)
{
    int idx = blockIdx.x * blockDim.x + threadIdx.x;
    if (idx >= X_ELEMS/4) return;
    int h4 = (idx & 31) * 4;
    float4 sc = *(const float4*)(g_xscale + h4);
    float4 sh = *(const float4*)(g_xshift + h4);
    float4 xn = *(const float4*)(g_xnew + idx*4);
    float4 xo = *(const float4*)(x + idx*4);
    float4 o;
    o.x = xo.x + fmaxf(0.f, xn.x*sc.x + sh.x);
    o.y = xo.y + fmaxf(0.f, xn.y*sc.y + sh.y);
    o.z = xo.z + fmaxf(0.f, xn.z*sc.z + sh.z);
    o.w = xo.w + fmaxf(0.f, xn.w*sc.w + sh.w);
    *(float4*)(out + idx*4) = o;
}

// 8 elements per thread: 1 uint4 (8 fp16 e_new) + 2 float4 (e) in, 2 float4 out
__global__ __launch_bounds__(256) void e_out_kernel(const float* __restrict__ e, float* __restrict__ out)
{
    size_t t = (size_t)blockIdx.x * 256 + threadIdx.x;   // 8-element group index
    size_t i = t * 8;                                     // element base
    int h0 = (int)(i & 127);
    float4 sc0 = *(const float4*)(g_escale + h0);
    float4 sh0 = *(const float4*)(g_eshift + h0);
    float4 sc1 = *(const float4*)(g_escale + h0 + 4);
    float4 sh1 = *(const float4*)(g_eshift + h0 + 4);
    uint4 raw = __ldcs((const uint4*)(g_e_tmp) + t);
    float4 e0 = __ldcs((const float4*)(e + i));
    float4 e1 = __ldcs((const float4*)(e + i + 4));
    float2 f0 = __half22float2(*(__half2*)&raw.x);
    float2 f1 = __half22float2(*(__half2*)&raw.y);
    float2 f2 = __half22float2(*(__half2*)&raw.z);
    float2 f3 = __half22float2(*(__half2*)&raw.w);
    float4 o0, o1;
    o0.x = e0.x + fmaxf(0.f, f0.x*sc0.x + sh0.x);
    o0.y = e0.y + fmaxf(0.f, f0.y*sc0.y + sh0.y);
    o0.z = e0.z + fmaxf(0.f, f1.x*sc0.z + sh0.z);
    o0.w = e0.w + fmaxf(0.f, f1.y*sc0.w + sh0.w);
    o1.x = e1.x + fmaxf(0.f, f2.x*sc1.x + sh1.x);
    o1.y = e1.y + fmaxf(0.f, f2.y*sc1.y + sh1.y);
    o1.z = e1.z + fmaxf(0.f, f3.x*sc1.z + sh1.z);
    o1.w = e1.w + fmaxf(0.f, f3.y*sc1.w + sh1.w);
    __stcs((float4*)(out + i), o0);
    __stcs((float4*)(out + i + 4), o1);
}

extern "C" void kernel_launch(void* const* d_in, const int* in_sizes, int n_in,
                              void* d_out, int out_size)
{
    const float* x    = (const float*)d_in[0];
    const float* e    = (const float*)d_in[1];
    const float* Ue_w = (const float*)d_in[2];
    const float* Ue_b = (const float*)d_in[3];
    const float* Ve_w = (const float*)d_in[4];
    const float* Ve_b = (const float*)d_in[5];
    const float* Un_w = (const float*)d_in[6];
    const float* Un_b = (const float*)d_in[7];
    const float* Vn_w = (const float*)d_in[8];
    const float* Vn_b = (const float*)d_in[9];
    const float* bne_w = (const float*)d_in[10];
    const float* bne_b = (const float*)d_in[11];
    const float* bnn_w = (const float*)d_in[12];
    const float* bnn_b = (const float*)d_in[13];
    float* out = (float*)d_out;

    cudaFuncSetAttribute(node_linear_kernel,
        cudaFuncAttributeMaxDynamicSharedMemorySize, NL_SMEM);
    cudaFuncSetAttribute(edge_fused_mma_kernel,
        cudaFuncAttributeMaxDynamicSharedMemorySize, EDGE_SMEM);

    node_linear_kernel<<<dim3(32, 3), 256, NL_SMEM>>>(x, Ve_w, Ve_b, Vn_w, Vn_b, Un_w, Un_b);

    edge_fused_mma_kernel<<<Bv*Nv, 256, EDGE_SMEM>>>(e, Ue_w, Ue_b);

    finalize_kernel<<<1, 128>>>(bne_w, bne_b, bnn_w, bnn_b);

    x_out_kernel<<<(X_ELEMS/4 + 255)/256, 256>>>(x, out);

    e_out_kernel<<<E_ELEMS/8/256, 256>>>(e, out + X_ELEMS);
}